// round 3
// baseline (speedup 1.0000x reference)
#include <cuda_runtime.h>
#include <math.h>

#define MM 8
#define BB 64
#define SS 128
#define DD 512
#define HH 8
#define FF 1024
#define HD 64           // head dim
#define MH 64           // MM*HH
#define GG 4

// ---------------- single scratch arena (static device global; no allocs) ----
// element offsets
#define O_Q   0u                          // [M,B,D]      q projection
#define O_TQ  262144u                     // [B,MH,D]     Wk^T-folded query
#define O_SC  2359296u                    // [B,MH,S]     scores / softmax w
#define O_U   2883584u                    // [B,MH,D]     w-weighted value_in
#define O_AO  4980736u                    // [M,B,D]      attention head out
#define O_X   5242880u                    // [M,B,2D]     relu(concat)
#define O_H   5767168u                    // [G,M,B,FF]   MLP hidden
#define O_HG  7864320u                    // [G,M,B,FF]   gate MLP hidden
#define O_OB  9961472u                    // [G,M,B,D]    MLP out (tanh relu)
#define O_GT  11010048u                   // [G,M,B]      sigmoid gates
#define SCRATCH_ELEMS 11012096u

__device__ float g_buf[SCRATCH_ELEMS];

// ---------------- generic batched SGEMM (rows fixed = 64) ----------------
// C[r,n] = sum_k A[r,k] * B[k,n]   (NN)   or   sum_k A[r,k] * Bt[n,k] (NT)
// batch z = z1*n2 + z2; per-tensor offsets off = z1*s?1 + z2*s?2.
// A: harness pointer, or nullptr -> g_buf + oA.  C: always g_buf + oC.
// epi: 0 none, 1 +bias, 2 relu(+bias), 3 tanh(relu(+bias))
struct GP {
    int N, K, lda, ldb, ldc, n2, epi;
    int sA1, sA2, sB1, sB2, sC1, sC2, sb1, sb2;
    unsigned oA, oC;
};

__global__ __launch_bounds__(256) void gemm_nn(
    const float* __restrict__ Ain, const float* __restrict__ Bm,
    const float* __restrict__ bias, GP p)
{
    __shared__ float As[16][68];
    __shared__ float Bs[16][132];

    const float* A = Ain ? Ain : g_buf + p.oA;
    float*       C = g_buf + p.oC;

    int z  = blockIdx.z;
    int z1 = z / p.n2, z2 = z - z1 * p.n2;
    A  += (size_t)z1 * p.sA1 + (size_t)z2 * p.sA2;
    Bm += (size_t)z1 * p.sB1 + (size_t)z2 * p.sB2;
    C  += (size_t)z1 * p.sC1 + (size_t)z2 * p.sC2;

    int n0  = blockIdx.x * 128;
    int tid = threadIdx.x;
    int tx  = tid & 15, ty = tid >> 4;

    float acc[4][8];
#pragma unroll
    for (int i = 0; i < 4; i++)
#pragma unroll
        for (int j = 0; j < 8; j++) acc[i][j] = 0.f;

    int a_row = tid >> 2;            // 0..63
    int a_k4  = (tid & 3) * 4;       // 0,4,8,12

    for (int kk = 0; kk < p.K; kk += 16) {
        float4 av = *(const float4*)&A[a_row * (size_t)p.lda + kk + a_k4];
        float4 bv[2];
#pragma unroll
        for (int t = 0; t < 2; t++) {
            int idx = tid + 256 * t;
            int bk  = idx >> 5;              // 0..15
            int bn4 = (idx & 31) * 4;        // 0..124
            if (n0 + bn4 < p.N)
                bv[t] = *(const float4*)&Bm[(kk + bk) * (size_t)p.ldb + n0 + bn4];
            else
                bv[t] = make_float4(0.f, 0.f, 0.f, 0.f);
        }
        __syncthreads();
        As[a_k4 + 0][a_row] = av.x;
        As[a_k4 + 1][a_row] = av.y;
        As[a_k4 + 2][a_row] = av.z;
        As[a_k4 + 3][a_row] = av.w;
#pragma unroll
        for (int t = 0; t < 2; t++) {
            int idx = tid + 256 * t;
            int bk  = idx >> 5;
            int bn4 = (idx & 31) * 4;
            *(float4*)&Bs[bk][bn4] = bv[t];
        }
        __syncthreads();
#pragma unroll
        for (int k = 0; k < 16; k++) {
            float4 af  = *(const float4*)&As[k][ty << 2];
            float4 bf0 = *(const float4*)&Bs[k][tx << 3];
            float4 bf1 = *(const float4*)&Bs[k][(tx << 3) + 4];
            float ar[4] = {af.x, af.y, af.z, af.w};
            float br[8] = {bf0.x, bf0.y, bf0.z, bf0.w, bf1.x, bf1.y, bf1.z, bf1.w};
#pragma unroll
            for (int i = 0; i < 4; i++)
#pragma unroll
                for (int j = 0; j < 8; j++) acc[i][j] += ar[i] * br[j];
        }
    }

    const float* bp = bias ? bias + (size_t)z1 * p.sb1 + (size_t)z2 * p.sb2 : nullptr;
#pragma unroll
    for (int i = 0; i < 4; i++) {
        int r = (ty << 2) + i;
#pragma unroll
        for (int j = 0; j < 8; j++) {
            int c = n0 + (tx << 3) + j;
            if (c < p.N) {
                float v = acc[i][j];
                if (p.epi >= 1) v += bp[c];
                if (p.epi == 2) v = fmaxf(v, 0.f);
                if (p.epi == 3) v = tanhf(fmaxf(v, 0.f));
                C[r * (size_t)p.ldc + c] = v;
            }
        }
    }
}

__global__ __launch_bounds__(256) void gemm_nt(
    const float* __restrict__ Ain, const float* __restrict__ Bt,
    const float* __restrict__ bias, GP p)
{
    __shared__ float As[16][68];
    __shared__ float Bs[16][132];

    const float* A = Ain ? Ain : g_buf + p.oA;
    float*       C = g_buf + p.oC;

    int z  = blockIdx.z;
    int z1 = z / p.n2, z2 = z - z1 * p.n2;
    A  += (size_t)z1 * p.sA1 + (size_t)z2 * p.sA2;
    Bt += (size_t)z1 * p.sB1 + (size_t)z2 * p.sB2;
    C  += (size_t)z1 * p.sC1 + (size_t)z2 * p.sC2;

    int n0  = blockIdx.x * 128;
    int tid = threadIdx.x;
    int tx  = tid & 15, ty = tid >> 4;

    float acc[4][8];
#pragma unroll
    for (int i = 0; i < 4; i++)
#pragma unroll
        for (int j = 0; j < 8; j++) acc[i][j] = 0.f;

    int a_row = tid >> 2;
    int a_k4  = (tid & 3) * 4;

    for (int kk = 0; kk < p.K; kk += 16) {
        float4 av = *(const float4*)&A[a_row * (size_t)p.lda + kk + a_k4];
        float4 bv[2];
#pragma unroll
        for (int t = 0; t < 2; t++) {
            int idx = tid + 256 * t;
            int bn  = idx >> 2;             // 0..127
            int bk4 = (idx & 3) * 4;        // 0,4,8,12
            bv[t] = *(const float4*)&Bt[(n0 + bn) * (size_t)p.ldb + kk + bk4];
        }
        __syncthreads();
        As[a_k4 + 0][a_row] = av.x;
        As[a_k4 + 1][a_row] = av.y;
        As[a_k4 + 2][a_row] = av.z;
        As[a_k4 + 3][a_row] = av.w;
#pragma unroll
        for (int t = 0; t < 2; t++) {
            int idx = tid + 256 * t;
            int bn  = idx >> 2;
            int bk4 = (idx & 3) * 4;
            Bs[bk4 + 0][bn] = bv[t].x;
            Bs[bk4 + 1][bn] = bv[t].y;
            Bs[bk4 + 2][bn] = bv[t].z;
            Bs[bk4 + 3][bn] = bv[t].w;
        }
        __syncthreads();
#pragma unroll
        for (int k = 0; k < 16; k++) {
            float4 af  = *(const float4*)&As[k][ty << 2];
            float4 bf0 = *(const float4*)&Bs[k][tx << 3];
            float4 bf1 = *(const float4*)&Bs[k][(tx << 3) + 4];
            float ar[4] = {af.x, af.y, af.z, af.w};
            float br[8] = {bf0.x, bf0.y, bf0.z, bf0.w, bf1.x, bf1.y, bf1.z, bf1.w};
#pragma unroll
            for (int i = 0; i < 4; i++)
#pragma unroll
                for (int j = 0; j < 8; j++) acc[i][j] += ar[i] * br[j];
        }
    }

    const float* bp = bias ? bias + (size_t)z1 * p.sb1 + (size_t)z2 * p.sb2 : nullptr;
#pragma unroll
    for (int i = 0; i < 4; i++) {
        int r = (ty << 2) + i;
#pragma unroll
        for (int j = 0; j < 8; j++) {
            int c = n0 + (tx << 3) + j;
            if (c < p.N) {
                float v = acc[i][j];
                if (p.epi >= 1) v += bp[c];
                if (p.epi == 2) v = fmaxf(v, 0.f);
                if (p.epi == 3) v = tanhf(fmaxf(v, 0.f));
                C[r * (size_t)p.ldc + c] = v;
            }
        }
    }
}

// ---------------- softmax over S=128 (fused 1/sqrt(hd) scale) ----------------
__global__ void softmax_k()
{
    float* sc = g_buf + O_SC;
    int row  = blockIdx.x * 8 + (threadIdx.x >> 5);   // B*MH = 4096 rows
    int lane = threadIdx.x & 31;
    float4 v = *(float4*)&sc[(size_t)row * SS + lane * 4];
    float mx = fmaxf(fmaxf(v.x, v.y), fmaxf(v.z, v.w));
#pragma unroll
    for (int o = 16; o; o >>= 1) mx = fmaxf(mx, __shfl_xor_sync(0xffffffffu, mx, o));
    float4 e;
    e.x = __expf((v.x - mx) * 0.125f);
    e.y = __expf((v.y - mx) * 0.125f);
    e.z = __expf((v.z - mx) * 0.125f);
    e.w = __expf((v.w - mx) * 0.125f);
    float s = e.x + e.y + e.z + e.w;
#pragma unroll
    for (int o = 16; o; o >>= 1) s += __shfl_xor_sync(0xffffffffu, s, o);
    float inv = 1.f / s;
    e.x *= inv; e.y *= inv; e.z *= inv; e.w *= inv;
    *(float4*)&sc[(size_t)row * SS + lane * 4] = e;
}

// ---------------- fill second half of x with relu(prev_state) ----------------
__global__ void xfill_k(const float* __restrict__ prev_state)
{
    int idx = blockIdx.x * 256 + threadIdx.x;         // M*B*D
    if (idx < MM * BB * DD) {
        int mb = idx / DD, j = idx - mb * DD;
        g_buf[O_X + (size_t)mb * (2 * DD) + DD + j] = fmaxf(prev_state[idx], 0.f);
    }
}

// ---------------- gate: sigmoid(hg . Wg2 + bg2), one warp per (g,m,b) --------
__global__ void gate_k(const float* __restrict__ Wg2, const float* __restrict__ bg2)
{
    int row  = blockIdx.x * 8 + (threadIdx.x >> 5);   // G*M*B = 2048 rows
    int lane = threadIdx.x & 31;
    int gm   = row / BB;
    const float* hg = g_buf + O_HG + (size_t)row * FF;
    const float* w  = &Wg2[(size_t)gm * FF];
    float s = 0.f;
#pragma unroll
    for (int f = lane * 4; f < FF; f += 128) {
        float4 a = *(const float4*)&hg[f];
        float4 b = *(const float4*)&w[f];
        s += a.x * b.x + a.y * b.y + a.z * b.z + a.w * b.w;
    }
#pragma unroll
    for (int o = 16; o; o >>= 1) s += __shfl_xor_sync(0xffffffffu, s, o);
    if (lane == 0)
        g_buf[O_GT + row] = 1.f / (1.f + __expf(-(s + bg2[gm])));
}

// ---------------- final gated combine, output order (state,query,key,value) --
__global__ void final_k(const float* __restrict__ pq, const float* __restrict__ pk,
                        const float* __restrict__ pv, const float* __restrict__ ps,
                        float* __restrict__ out)
{
    int idx = blockIdx.x * 256 + threadIdx.x;         // 4*M*B*D
    int o   = idx / (MM * BB * DD);
    int rem = idx - o * (MM * BB * DD);
    int mb  = rem / DD;
    int g   = (o == 0) ? 3 : (o - 1);                 // out0=state(g3),1=query(g0),2=key(g1),3=value(g2)
    const float* prev = (o == 0) ? ps : (o == 1) ? pq : (o == 2) ? pk : pv;
    float gt = g_buf[O_GT + g * MM * BB + mb];
    float ov = g_buf[O_OB + (size_t)g * MM * BB * DD + rem];
    out[idx] = gt * ov + (1.f - gt) * prev[rem];
}

// ---------------- launch ----------------
static GP mk(int N, int K, int lda, int ldb, int ldc, int n2, int epi,
             int sA1, int sA2, int sB1, int sB2, int sC1, int sC2, int sb1, int sb2,
             unsigned oA, unsigned oC)
{
    GP p; p.N = N; p.K = K; p.lda = lda; p.ldb = ldb; p.ldc = ldc; p.n2 = n2; p.epi = epi;
    p.sA1 = sA1; p.sA2 = sA2; p.sB1 = sB1; p.sB2 = sB2; p.sC1 = sC1; p.sC2 = sC2;
    p.sb1 = sb1; p.sb2 = sb2; p.oA = oA; p.oC = oC;
    return p;
}

extern "C" void kernel_launch(void* const* d_in, const int* in_sizes, int n_in,
                              void* d_out, int out_size)
{
    const float* prev_state = (const float*)d_in[0];
    const float* prev_query = (const float*)d_in[1];
    const float* prev_key   = (const float*)d_in[2];
    const float* prev_value = (const float*)d_in[3];
    const float* key_in     = (const float*)d_in[4];
    const float* value_in   = (const float*)d_in[5];
    const float* Wq  = (const float*)d_in[6];
    const float* bq  = (const float*)d_in[7];
    const float* Wk  = (const float*)d_in[8];
    // bk (d_in[9]) is provably dead: its score contribution is constant over s -> softmax-invariant.
    const float* Wv  = (const float*)d_in[10];
    const float* bv  = (const float*)d_in[11];
    const float* Wo  = (const float*)d_in[12];
    const float* bo  = (const float*)d_in[13];
    const float* W1  = (const float*)d_in[14];
    const float* b1  = (const float*)d_in[15];
    const float* W2  = (const float*)d_in[16];
    const float* b2  = (const float*)d_in[17];
    const float* Wg1 = (const float*)d_in[18];
    const float* bg1 = (const float*)d_in[19];
    const float* Wg2 = (const float*)d_in[20];
    const float* bg2 = (const float*)d_in[21];

    // K1: q = prev_query @ Wq + bq              [per m: 64x512x512, NN]
    gemm_nn<<<dim3(4, 1, MM), 256>>>(prev_query, Wq, bq,
        mk(DD, DD, DD, DD, DD, 1, 1,  BB*DD,0,  DD*DD,0,  BB*DD,0,  DD,0,  0, O_Q));

    // K2: tq[b,mh,k] = sum_j q[m,b,h*hd+j] * Wk[m,k,h*hd+j]   [per (m,h): 64x512x64, NT]
    gemm_nt<<<dim3(4, 1, MM*HH), 256>>>(nullptr, Wk, nullptr,
        mk(DD, HD, DD, DD, MH*DD, HH, 0,  BB*DD,HD,  DD*DD,HD,  HH*DD,DD,  0,0,  O_Q, O_TQ));

    // K3: scores[b,mh,s] = key_in[s,b,:] . tq[b,mh,:]         [per b: 64x128x512, NT]
    gemm_nt<<<dim3(1, 1, BB), 256>>>(nullptr, key_in, nullptr,
        mk(SS, DD, DD, BB*DD, SS, 1, 0,  MH*DD,0,  DD,0,  MH*SS,0,  0,0,  O_TQ, O_SC));

    // softmax over s (scale 1/8 fused)
    softmax_k<<<BB*MH/8, 256>>>();

    // K4: u[b,mh,k] = sum_s w[b,mh,s] * value_in[s,b,k]       [per b: 64x512x128, NN]
    gemm_nn<<<dim3(4, 1, BB), 256>>>(nullptr, value_in, nullptr,
        mk(DD, SS, SS, BB*DD, DD, 1, 0,  MH*SS,0,  DD,0,  MH*DD,0,  0,0,  O_SC, O_U));

    // K5: ao[m,b,h*hd+j] = sum_k u[b,mh,k] * Wv[m,k,h*hd+j] + bv  [per (m,h): 64x64x512, NN]
    gemm_nn<<<dim3(1, 1, MM*HH), 256>>>(nullptr, Wv, bv,
        mk(HD, DD, MH*DD, DD, DD, HH, 1,  HH*DD,DD,  DD*DD,HD,  BB*DD,HD,  DD,HD,  O_U, O_AO));

    // K6: x[:, :D] = relu(ao @ Wo + bo)                        [per m: 64x512x512, NN]
    gemm_nn<<<dim3(4, 1, MM), 256>>>(nullptr, Wo, bo,
        mk(DD, DD, DD, DD, 2*DD, 1, 2,  BB*DD,0,  DD*DD,0,  BB*2*DD,0,  DD,0,  O_AO, O_X));

    // x[:, D:] = relu(prev_state)
    xfill_k<<<(MM*BB*DD)/256, 256>>>(prev_state);

    // K7a: h = relu(x @ W1 + b1)                [per (g,m): 64x1024x1024, NN]
    gemm_nn<<<dim3(8, 1, GG*MM), 256>>>(nullptr, W1, b1,
        mk(FF, 2*DD, 2*DD, FF, FF, MM, 2,  0,BB*2*DD,  MM*2*DD*FF,2*DD*FF,  MM*BB*FF,BB*FF,  MM*FF,FF,  O_X, O_H));

    // K7b: hg = relu(x @ Wg1 + bg1)
    gemm_nn<<<dim3(8, 1, GG*MM), 256>>>(nullptr, Wg1, bg1,
        mk(FF, 2*DD, 2*DD, FF, FF, MM, 2,  0,BB*2*DD,  MM*2*DD*FF,2*DD*FF,  MM*BB*FF,BB*FF,  MM*FF,FF,  O_X, O_HG));

    // K8a: ob = tanh(relu(h @ W2 + b2))         [per (g,m): 64x512x1024, NN]
    gemm_nn<<<dim3(4, 1, GG*MM), 256>>>(nullptr, W2, b2,
        mk(DD, FF, FF, DD, DD, MM, 3,  MM*BB*FF,BB*FF,  MM*FF*DD,FF*DD,  MM*BB*DD,BB*DD,  MM*DD,DD,  O_H, O_OB));

    // K8b: gates
    gate_k<<<GG*MM*BB/8, 256>>>(Wg2, bg2);

    // K9: gated combine + output reorder
    final_k<<<(GG*MM*BB*DD)/256, 256>>>(prev_query, prev_key, prev_value, prev_state,
                                        (float*)d_out);
}

// round 5
// speedup vs baseline: 1.0041x; 1.0041x over previous
#include <cuda_runtime.h>
#include <math.h>

#define MM 8
#define BB 64
#define SS 128
#define DD 512
#define HH 8
#define FF 1024
#define HD 64           // head dim
#define MH 64           // MM*HH
#define GG 4

// ---------------- single scratch arena (static device global; no allocs) ----
// element offsets
#define O_Q   0u                          // [M,B,D]      q projection
#define O_TQ  262144u                     // [B,MH,D]     Wk^T-folded query
#define O_SC  2359296u                    // [B,MH,S]     scores / softmax w
#define O_U   2883584u                    // [B,MH,D]     w-weighted value_in
#define O_AO  4980736u                    // [M,B,D]      attention head out
#define O_X   5242880u                    // [M,B,2D]     relu(concat)
#define O_H   5767168u                    // [G,M,B,FF]   MLP hidden
#define O_HG  7864320u                    // [G,M,B,FF]   gate MLP hidden
#define O_OB  9961472u                    // [G,M,B,D]    MLP out (tanh relu)
#define O_GT  11010048u                   // [G,M,B]      sigmoid gates
#define SCRATCH_ELEMS 11012096u

__device__ float g_buf[SCRATCH_ELEMS];

// ---------------- generic batched SGEMM (rows fixed = 64) ----------------
// C[r,n] = sum_k A[r,k] * B[k,n]   (NN)   or   sum_k A[r,k] * Bt[n,k] (NT)
// batch z = z1*n2 + z2; per-tensor offsets off = z1*s?1 + z2*s?2.
// A: harness pointer, or nullptr -> g_buf + oA.  C: always g_buf + oC.
// epi: 0 none, 1 +bias, 2 relu(+bias), 3 tanh(relu(+bias))
struct GP {
    int N, K, lda, ldb, ldc, n2, epi;
    int sA1, sA2, sB1, sB2, sC1, sC2, sb1, sb2;
    unsigned oA, oC;
};

__global__ __launch_bounds__(256) void gemm_nn(
    const float* __restrict__ Ain, const float* __restrict__ Bm,
    const float* __restrict__ bias, GP p)
{
    __shared__ float As[16][68];
    __shared__ float Bs[16][132];

    const float* A = Ain ? Ain : g_buf + p.oA;
    float*       C = g_buf + p.oC;

    int z  = blockIdx.z;
    int z1 = z / p.n2, z2 = z - z1 * p.n2;
    A  += (size_t)z1 * p.sA1 + (size_t)z2 * p.sA2;
    Bm += (size_t)z1 * p.sB1 + (size_t)z2 * p.sB2;
    C  += (size_t)z1 * p.sC1 + (size_t)z2 * p.sC2;

    int n0  = blockIdx.x * 128;
    int tid = threadIdx.x;
    int tx  = tid & 15, ty = tid >> 4;

    float acc[4][8];
#pragma unroll
    for (int i = 0; i < 4; i++)
#pragma unroll
        for (int j = 0; j < 8; j++) acc[i][j] = 0.f;

    int a_row = tid >> 2;            // 0..63
    int a_k4  = (tid & 3) * 4;       // 0,4,8,12

    for (int kk = 0; kk < p.K; kk += 16) {
        float4 av = *(const float4*)&A[a_row * (size_t)p.lda + kk + a_k4];
        float4 bv[2];
#pragma unroll
        for (int t = 0; t < 2; t++) {
            int idx = tid + 256 * t;
            int bk  = idx >> 5;              // 0..15
            int bn4 = (idx & 31) * 4;        // 0..124
            if (n0 + bn4 < p.N)
                bv[t] = *(const float4*)&Bm[(kk + bk) * (size_t)p.ldb + n0 + bn4];
            else
                bv[t] = make_float4(0.f, 0.f, 0.f, 0.f);
        }
        __syncthreads();
        As[a_k4 + 0][a_row] = av.x;
        As[a_k4 + 1][a_row] = av.y;
        As[a_k4 + 2][a_row] = av.z;
        As[a_k4 + 3][a_row] = av.w;
#pragma unroll
        for (int t = 0; t < 2; t++) {
            int idx = tid + 256 * t;
            int bk  = idx >> 5;
            int bn4 = (idx & 31) * 4;
            *(float4*)&Bs[bk][bn4] = bv[t];
        }
        __syncthreads();
#pragma unroll
        for (int k = 0; k < 16; k++) {
            float4 af  = *(const float4*)&As[k][ty << 2];
            float4 bf0 = *(const float4*)&Bs[k][tx << 3];
            float4 bf1 = *(const float4*)&Bs[k][(tx << 3) + 4];
            float ar[4] = {af.x, af.y, af.z, af.w};
            float br[8] = {bf0.x, bf0.y, bf0.z, bf0.w, bf1.x, bf1.y, bf1.z, bf1.w};
#pragma unroll
            for (int i = 0; i < 4; i++)
#pragma unroll
                for (int j = 0; j < 8; j++) acc[i][j] += ar[i] * br[j];
        }
    }

    const float* bp = bias ? bias + (size_t)z1 * p.sb1 + (size_t)z2 * p.sb2 : nullptr;
#pragma unroll
    for (int i = 0; i < 4; i++) {
        int r = (ty << 2) + i;
#pragma unroll
        for (int j = 0; j < 8; j++) {
            int c = n0 + (tx << 3) + j;
            if (c < p.N) {
                float v = acc[i][j];
                if (p.epi >= 1) v += bp[c];
                if (p.epi == 2) v = fmaxf(v, 0.f);
                if (p.epi == 3) v = tanhf(fmaxf(v, 0.f));
                C[r * (size_t)p.ldc + c] = v;
            }
        }
    }
}

__global__ __launch_bounds__(256) void gemm_nt(
    const float* __restrict__ Ain, const float* __restrict__ Bt,
    const float* __restrict__ bias, GP p)
{
    __shared__ float As[16][68];
    __shared__ float Bs[16][132];

    const float* A = Ain ? Ain : g_buf + p.oA;
    float*       C = g_buf + p.oC;

    int z  = blockIdx.z;
    int z1 = z / p.n2, z2 = z - z1 * p.n2;
    A  += (size_t)z1 * p.sA1 + (size_t)z2 * p.sA2;
    Bt += (size_t)z1 * p.sB1 + (size_t)z2 * p.sB2;
    C  += (size_t)z1 * p.sC1 + (size_t)z2 * p.sC2;

    int n0  = blockIdx.x * 128;
    int tid = threadIdx.x;
    int tx  = tid & 15, ty = tid >> 4;

    float acc[4][8];
#pragma unroll
    for (int i = 0; i < 4; i++)
#pragma unroll
        for (int j = 0; j < 8; j++) acc[i][j] = 0.f;

    int a_row = tid >> 2;
    int a_k4  = (tid & 3) * 4;

    for (int kk = 0; kk < p.K; kk += 16) {
        float4 av = *(const float4*)&A[a_row * (size_t)p.lda + kk + a_k4];
        float4 bv[2];
#pragma unroll
        for (int t = 0; t < 2; t++) {
            int idx = tid + 256 * t;
            int bn  = idx >> 2;             // 0..127
            int bk4 = (idx & 3) * 4;        // 0,4,8,12
            bv[t] = *(const float4*)&Bt[(n0 + bn) * (size_t)p.ldb + kk + bk4];
        }
        __syncthreads();
        As[a_k4 + 0][a_row] = av.x;
        As[a_k4 + 1][a_row] = av.y;
        As[a_k4 + 2][a_row] = av.z;
        As[a_k4 + 3][a_row] = av.w;
#pragma unroll
        for (int t = 0; t < 2; t++) {
            int idx = tid + 256 * t;
            int bn  = idx >> 2;
            int bk4 = (idx & 3) * 4;
            Bs[bk4 + 0][bn] = bv[t].x;
            Bs[bk4 + 1][bn] = bv[t].y;
            Bs[bk4 + 2][bn] = bv[t].z;
            Bs[bk4 + 3][bn] = bv[t].w;
        }
        __syncthreads();
#pragma unroll
        for (int k = 0; k < 16; k++) {
            float4 af  = *(const float4*)&As[k][ty << 2];
            float4 bf0 = *(const float4*)&Bs[k][tx << 3];
            float4 bf1 = *(const float4*)&Bs[k][(tx << 3) + 4];
            float ar[4] = {af.x, af.y, af.z, af.w};
            float br[8] = {bf0.x, bf0.y, bf0.z, bf0.w, bf1.x, bf1.y, bf1.z, bf1.w};
#pragma unroll
            for (int i = 0; i < 4; i++)
#pragma unroll
                for (int j = 0; j < 8; j++) acc[i][j] += ar[i] * br[j];
        }
    }

    const float* bp = bias ? bias + (size_t)z1 * p.sb1 + (size_t)z2 * p.sb2 : nullptr;
#pragma unroll
    for (int i = 0; i < 4; i++) {
        int r = (ty << 2) + i;
#pragma unroll
        for (int j = 0; j < 8; j++) {
            int c = n0 + (tx << 3) + j;
            if (c < p.N) {
                float v = acc[i][j];
                if (p.epi >= 1) v += bp[c];
                if (p.epi == 2) v = fmaxf(v, 0.f);
                if (p.epi == 3) v = tanhf(fmaxf(v, 0.f));
                C[r * (size_t)p.ldc + c] = v;
            }
        }
    }
}

// ---------------- softmax over S=128 (fused 1/sqrt(hd) scale) ----------------
__global__ void softmax_k()
{
    float* sc = g_buf + O_SC;
    int row  = blockIdx.x * 8 + (threadIdx.x >> 5);   // B*MH = 4096 rows
    int lane = threadIdx.x & 31;
    float4 v = *(float4*)&sc[(size_t)row * SS + lane * 4];
    float mx = fmaxf(fmaxf(v.x, v.y), fmaxf(v.z, v.w));
#pragma unroll
    for (int o = 16; o; o >>= 1) mx = fmaxf(mx, __shfl_xor_sync(0xffffffffu, mx, o));
    float4 e;
    e.x = __expf((v.x - mx) * 0.125f);
    e.y = __expf((v.y - mx) * 0.125f);
    e.z = __expf((v.z - mx) * 0.125f);
    e.w = __expf((v.w - mx) * 0.125f);
    float s = e.x + e.y + e.z + e.w;
#pragma unroll
    for (int o = 16; o; o >>= 1) s += __shfl_xor_sync(0xffffffffu, s, o);
    float inv = 1.f / s;
    e.x *= inv; e.y *= inv; e.z *= inv; e.w *= inv;
    *(float4*)&sc[(size_t)row * SS + lane * 4] = e;
}

// ---------------- fill second half of x with relu(prev_state) ----------------
__global__ void xfill_k(const float* __restrict__ prev_state)
{
    int idx = blockIdx.x * 256 + threadIdx.x;         // M*B*D
    if (idx < MM * BB * DD) {
        int mb = idx / DD, j = idx - mb * DD;
        g_buf[O_X + (size_t)mb * (2 * DD) + DD + j] = fmaxf(prev_state[idx], 0.f);
    }
}

// ---------------- gate: sigmoid(hg . Wg2 + bg2), one warp per (g,m,b) --------
__global__ void gate_k(const float* __restrict__ Wg2, const float* __restrict__ bg2)
{
    int row  = blockIdx.x * 8 + (threadIdx.x >> 5);   // G*M*B = 2048 rows
    int lane = threadIdx.x & 31;
    int gm   = row / BB;
    const float* hg = g_buf + O_HG + (size_t)row * FF;
    const float* w  = &Wg2[(size_t)gm * FF];
    float s = 0.f;
#pragma unroll
    for (int f = lane * 4; f < FF; f += 128) {
        float4 a = *(const float4*)&hg[f];
        float4 b = *(const float4*)&w[f];
        s += a.x * b.x + a.y * b.y + a.z * b.z + a.w * b.w;
    }
#pragma unroll
    for (int o = 16; o; o >>= 1) s += __shfl_xor_sync(0xffffffffu, s, o);
    if (lane == 0)
        g_buf[O_GT + row] = 1.f / (1.f + __expf(-(s + bg2[gm])));
}

// ---------------- final gated combine, output order (state,query,key,value) --
__global__ void final_k(const float* __restrict__ pq, const float* __restrict__ pk,
                        const float* __restrict__ pv, const float* __restrict__ ps,
                        float* __restrict__ out)
{
    int idx = blockIdx.x * 256 + threadIdx.x;         // 4*M*B*D
    int o   = idx / (MM * BB * DD);
    int rem = idx - o * (MM * BB * DD);
    int mb  = rem / DD;
    int g   = (o == 0) ? 3 : (o - 1);                 // out0=state(g3),1=query(g0),2=key(g1),3=value(g2)
    const float* prev = (o == 0) ? ps : (o == 1) ? pq : (o == 2) ? pk : pv;
    float gt = g_buf[O_GT + g * MM * BB + mb];
    float ov = g_buf[O_OB + (size_t)g * MM * BB * DD + rem];
    out[idx] = gt * ov + (1.f - gt) * prev[rem];
}

// ---------------- launch ----------------
static GP mk(int N, int K, int lda, int ldb, int ldc, int n2, int epi,
             int sA1, int sA2, int sB1, int sB2, int sC1, int sC2, int sb1, int sb2,
             unsigned oA, unsigned oC)
{
    GP p; p.N = N; p.K = K; p.lda = lda; p.ldb = ldb; p.ldc = ldc; p.n2 = n2; p.epi = epi;
    p.sA1 = sA1; p.sA2 = sA2; p.sB1 = sB1; p.sB2 = sB2; p.sC1 = sC1; p.sC2 = sC2;
    p.sb1 = sb1; p.sb2 = sb2; p.oA = oA; p.oC = oC;
    return p;
}

extern "C" void kernel_launch(void* const* d_in, const int* in_sizes, int n_in,
                              void* d_out, int out_size)
{
    const float* prev_state = (const float*)d_in[0];
    const float* prev_query = (const float*)d_in[1];
    const float* prev_key   = (const float*)d_in[2];
    const float* prev_value = (const float*)d_in[3];
    const float* key_in     = (const float*)d_in[4];
    const float* value_in   = (const float*)d_in[5];
    const float* Wq  = (const float*)d_in[6];
    const float* bq  = (const float*)d_in[7];
    const float* Wk  = (const float*)d_in[8];
    // bk (d_in[9]) is provably dead: its score contribution is constant over s -> softmax-invariant.
    const float* Wv  = (const float*)d_in[10];
    const float* bv  = (const float*)d_in[11];
    const float* Wo  = (const float*)d_in[12];
    const float* bo  = (const float*)d_in[13];
    const float* W1  = (const float*)d_in[14];
    const float* b1  = (const float*)d_in[15];
    const float* W2  = (const float*)d_in[16];
    const float* b2  = (const float*)d_in[17];
    const float* Wg1 = (const float*)d_in[18];
    const float* bg1 = (const float*)d_in[19];
    const float* Wg2 = (const float*)d_in[20];
    const float* bg2 = (const float*)d_in[21];

    // K1: q = prev_query @ Wq + bq              [per m: 64x512x512, NN]
    gemm_nn<<<dim3(4, 1, MM), 256>>>(prev_query, Wq, bq,
        mk(DD, DD, DD, DD, DD, 1, 1,  BB*DD,0,  DD*DD,0,  BB*DD,0,  DD,0,  0, O_Q));

    // K2: tq[b,mh,k] = sum_j q[m,b,h*hd+j] * Wk[m,k,h*hd+j]   [per (m,h): 64x512x64, NT]
    gemm_nt<<<dim3(4, 1, MM*HH), 256>>>(nullptr, Wk, nullptr,
        mk(DD, HD, DD, DD, MH*DD, HH, 0,  BB*DD,HD,  DD*DD,HD,  HH*DD,DD,  0,0,  O_Q, O_TQ));

    // K3: scores[b,mh,s] = key_in[s,b,:] . tq[b,mh,:]         [per b: 64x128x512, NT]
    gemm_nt<<<dim3(1, 1, BB), 256>>>(nullptr, key_in, nullptr,
        mk(SS, DD, DD, BB*DD, SS, 1, 0,  MH*DD,0,  DD,0,  MH*SS,0,  0,0,  O_TQ, O_SC));

    // softmax over s (scale 1/8 fused)
    softmax_k<<<BB*MH/8, 256>>>();

    // K4: u[b,mh,k] = sum_s w[b,mh,s] * value_in[s,b,k]       [per b: 64x512x128, NN]
    gemm_nn<<<dim3(4, 1, BB), 256>>>(nullptr, value_in, nullptr,
        mk(DD, SS, SS, BB*DD, DD, 1, 0,  MH*SS,0,  DD,0,  MH*DD,0,  0,0,  O_SC, O_U));

    // K5: ao[m,b,h*hd+j] = sum_k u[b,mh,k] * Wv[m,k,h*hd+j] + bv  [per (m,h): 64x64x512, NN]
    gemm_nn<<<dim3(1, 1, MM*HH), 256>>>(nullptr, Wv, bv,
        mk(HD, DD, MH*DD, DD, DD, HH, 1,  HH*DD,DD,  DD*DD,HD,  BB*DD,HD,  DD,HD,  O_U, O_AO));

    // K6: x[:, :D] = relu(ao @ Wo + bo)                        [per m: 64x512x512, NN]
    gemm_nn<<<dim3(4, 1, MM), 256>>>(nullptr, Wo, bo,
        mk(DD, DD, DD, DD, 2*DD, 1, 2,  BB*DD,0,  DD*DD,0,  BB*2*DD,0,  DD,0,  O_AO, O_X));

    // x[:, D:] = relu(prev_state)
    xfill_k<<<(MM*BB*DD)/256, 256>>>(prev_state);

    // K7a: h = relu(x @ W1 + b1)                [per (g,m): 64x1024x1024, NN]
    gemm_nn<<<dim3(8, 1, GG*MM), 256>>>(nullptr, W1, b1,
        mk(FF, 2*DD, 2*DD, FF, FF, MM, 2,  0,BB*2*DD,  MM*2*DD*FF,2*DD*FF,  MM*BB*FF,BB*FF,  MM*FF,FF,  O_X, O_H));

    // K7b: hg = relu(x @ Wg1 + bg1)
    gemm_nn<<<dim3(8, 1, GG*MM), 256>>>(nullptr, Wg1, bg1,
        mk(FF, 2*DD, 2*DD, FF, FF, MM, 2,  0,BB*2*DD,  MM*2*DD*FF,2*DD*FF,  MM*BB*FF,BB*FF,  MM*FF,FF,  O_X, O_HG));

    // K8a: ob = tanh(relu(h @ W2 + b2))         [per (g,m): 64x512x1024, NN]
    gemm_nn<<<dim3(4, 1, GG*MM), 256>>>(nullptr, W2, b2,
        mk(DD, FF, FF, DD, DD, MM, 3,  MM*BB*FF,BB*FF,  MM*FF*DD,FF*DD,  MM*BB*DD,BB*DD,  MM*DD,DD,  O_H, O_OB));

    // K8b: gates
    gate_k<<<GG*MM*BB/8, 256>>>(Wg2, bg2);

    // K9: gated combine + output reorder
    final_k<<<(GG*MM*BB*DD)/256, 256>>>(prev_query, prev_key, prev_value, prev_state,
                                        (float*)d_out);
}

// round 7
// speedup vs baseline: 1.8839x; 1.8763x over previous
#include <cuda_runtime.h>
#include <math.h>
#include <stdint.h>

#define MM 8
#define BB 64
#define SS 128
#define DD 512
#define HH 8
#define FF 1024
#define HD 64
#define MH 64
#define GG 4

#define O_Q   0u
#define O_TQ  262144u
#define O_SC  2359296u
#define O_U   2883584u
#define O_AO  4980736u
#define O_X   5242880u
#define O_H   5767168u
#define O_HG  7864320u
#define O_OB  9961472u
#define O_GT  11010048u
#define SCRATCH_ELEMS 11012096u

__device__ float g_buf[SCRATCH_ELEMS];

// ===================== helpers =====================
__device__ __forceinline__ uint32_t t32(float x) {
    uint32_t r;
    asm("cvt.rna.tf32.f32 %0, %1;" : "=r"(r) : "f"(x));
    return r;
}

__device__ __forceinline__ void mma8(float* c, const uint32_t* a, uint32_t b0, uint32_t b1) {
    asm volatile("mma.sync.aligned.m16n8k8.row.col.f32.tf32.tf32.f32 "
        "{%0,%1,%2,%3}, {%4,%5,%6,%7}, {%8,%9}, {%0,%1,%2,%3};"
        : "+f"(c[0]), "+f"(c[1]), "+f"(c[2]), "+f"(c[3])
        : "r"(a[0]), "r"(a[1]), "r"(a[2]), "r"(a[3]), "r"(b0), "r"(b1));
}

// D[f,b] = sum_k W[f,k]*A[b,k]; C[b*ldc+f]
// trans=1: W gmem [k][f]; trans=0: W gmem [f][k].
// epi: 0 none, 1 +bias, 2 relu+bias, 3 tanh(relu+bias)
struct TGP {
    int K, ldW, ldA, ldc, n2, trans, epi;
    int sW1, sW2, sA1, sA2, sC1, sC2, sb1, sb2;
    unsigned oW, oA, oC;
};

// ===================== single-product tf32 GEMM (K-tile 32) =====================
__global__ __launch_bounds__(256) void mma_gemm1(
    const float* __restrict__ Wg, const float* __restrict__ Ag,
    const float* __restrict__ bias, TGP p)
{
    __shared__ uint32_t As[128 * 36];
    __shared__ uint32_t Bs[64 * 36];

    int tid = threadIdx.x, wid = tid >> 5, lane = tid & 31;
    int tg = lane >> 2, tq = lane & 3;
    int z = blockIdx.z, z1 = z / p.n2, z2 = z - z1 * p.n2;
    int f0 = blockIdx.x * 128;

    const float* Wp = (Wg ? Wg : g_buf + p.oW) + (size_t)z1 * p.sW1 + (size_t)z2 * p.sW2;
    const float* Ap = (Ag ? Ag : g_buf + p.oA) + (size_t)z1 * p.sA1 + (size_t)z2 * p.sA2;
    float*       Cp = g_buf + p.oC + (size_t)z1 * p.sC1 + (size_t)z2 * p.sC2;

    int fw = (wid & 3) * 32, bw = (wid >> 2) * 32;
    float acc[2][4][4];
#pragma unroll
    for (int i = 0; i < 2; i++)
#pragma unroll
        for (int j = 0; j < 4; j++)
#pragma unroll
            for (int r = 0; r < 4; r++) acc[i][j][r] = 0.f;

    for (int kk = 0; kk < p.K; kk += 32) {
        float4 wv[4], av[2];
        if (p.trans) {
#pragma unroll
            for (int i = 0; i < 4; i++) {
                int idx = tid + 256 * i;
                int k = idx >> 5;                       // wid + 8i
                wv[i] = *(const float4*)&Wp[(size_t)(kk + k) * p.ldW + f0 + 4 * lane];
            }
        } else {
#pragma unroll
            for (int i = 0; i < 4; i++) {
                int idx = tid + 256 * i;
                int f = idx >> 3, kq = (idx & 7) * 4;
                wv[i] = *(const float4*)&Wp[(size_t)(f0 + f) * p.ldW + kk + kq];
            }
        }
#pragma unroll
        for (int i = 0; i < 2; i++) {
            int idx = tid + 256 * i;
            int b = idx >> 3, kq = (idx & 7) * 4;
            av[i] = *(const float4*)&Ap[(size_t)b * p.ldA + kk + kq];
        }
        __syncthreads();
        if (p.trans) {
#pragma unroll
            for (int i = 0; i < 4; i++) {
                int idx = tid + 256 * i;
                int k = idx >> 5;
                float w4[4] = {wv[i].x, wv[i].y, wv[i].z, wv[i].w};
#pragma unroll
                for (int j = 0; j < 4; j++) {
                    int c = (j + lane) & 3;
                    As[(4 * lane + c) * 36 + k] = t32(w4[c]);
                }
            }
        } else {
#pragma unroll
            for (int i = 0; i < 4; i++) {
                int idx = tid + 256 * i;
                int f = idx >> 3, kq = (idx & 7) * 4;
                As[f * 36 + kq + 0] = t32(wv[i].x);
                As[f * 36 + kq + 1] = t32(wv[i].y);
                As[f * 36 + kq + 2] = t32(wv[i].z);
                As[f * 36 + kq + 3] = t32(wv[i].w);
            }
        }
#pragma unroll
        for (int i = 0; i < 2; i++) {
            int idx = tid + 256 * i;
            int b = idx >> 3, kq = (idx & 7) * 4;
            Bs[b * 36 + kq + 0] = t32(av[i].x);
            Bs[b * 36 + kq + 1] = t32(av[i].y);
            Bs[b * 36 + kq + 2] = t32(av[i].z);
            Bs[b * 36 + kq + 3] = t32(av[i].w);
        }
        __syncthreads();

#pragma unroll
        for (int s = 0; s < 4; s++) {
            uint32_t a[2][4], bq[4][2];
#pragma unroll
            for (int i = 0; i < 2; i++) {
                int fb = fw + 16 * i + tg;
                a[i][0] = As[fb * 36 + 8 * s + tq];
                a[i][1] = As[(fb + 8) * 36 + 8 * s + tq];
                a[i][2] = As[fb * 36 + 8 * s + tq + 4];
                a[i][3] = As[(fb + 8) * 36 + 8 * s + tq + 4];
            }
#pragma unroll
            for (int j = 0; j < 4; j++) {
                int nb = bw + 8 * j + tg;
                bq[j][0] = Bs[nb * 36 + 8 * s + tq];
                bq[j][1] = Bs[nb * 36 + 8 * s + tq + 4];
            }
#pragma unroll
            for (int i = 0; i < 2; i++)
#pragma unroll
                for (int j = 0; j < 4; j++)
                    mma8(acc[i][j], a[i], bq[j][0], bq[j][1]);
        }
        __syncthreads();
    }

    const float* bp = (p.epi >= 1) ? bias + (size_t)z1 * p.sb1 + (size_t)z2 * p.sb2 : nullptr;
#pragma unroll
    for (int i = 0; i < 2; i++) {
        int fr = f0 + fw + 16 * i + tg, frh = fr + 8;
        float bv0 = bp ? bp[fr] : 0.f, bv1 = bp ? bp[frh] : 0.f;
#pragma unroll
        for (int j = 0; j < 4; j++) {
            int bc = bw + 8 * j + 2 * tq;
            float v0 = acc[i][j][0] + bv0, v1 = acc[i][j][1] + bv0;
            float v2 = acc[i][j][2] + bv1, v3 = acc[i][j][3] + bv1;
            if (p.epi == 2) {
                v0 = fmaxf(v0, 0.f); v1 = fmaxf(v1, 0.f);
                v2 = fmaxf(v2, 0.f); v3 = fmaxf(v3, 0.f);
            } else if (p.epi == 3) {
                v0 = tanhf(fmaxf(v0, 0.f)); v1 = tanhf(fmaxf(v1, 0.f));
                v2 = tanhf(fmaxf(v2, 0.f)); v3 = tanhf(fmaxf(v3, 0.f));
            }
            Cp[(size_t)bc * p.ldc + fr]        = v0;
            Cp[(size_t)(bc + 1) * p.ldc + fr]  = v1;
            Cp[(size_t)bc * p.ldc + frh]       = v2;
            Cp[(size_t)(bc + 1) * p.ldc + frh] = v3;
        }
    }
}

// ===================== 3xTF32 split GEMM (K-tile 16, fp32-accurate) ============
__global__ __launch_bounds__(256) void mma_gemm3(
    const float* __restrict__ Wg, const float* __restrict__ Ag,
    const float* __restrict__ bias, TGP p)
{
    __shared__ uint32_t Ah[128 * 20], Al[128 * 20];
    __shared__ uint32_t Bh[64 * 20],  Bl[64 * 20];

    int tid = threadIdx.x, wid = tid >> 5, lane = tid & 31;
    int tg = lane >> 2, tq = lane & 3;
    int z = blockIdx.z, z1 = z / p.n2, z2 = z - z1 * p.n2;
    int f0 = blockIdx.x * 128;

    const float* Wp = (Wg ? Wg : g_buf + p.oW) + (size_t)z1 * p.sW1 + (size_t)z2 * p.sW2;
    const float* Ap = (Ag ? Ag : g_buf + p.oA) + (size_t)z1 * p.sA1 + (size_t)z2 * p.sA2;
    float*       Cp = g_buf + p.oC + (size_t)z1 * p.sC1 + (size_t)z2 * p.sC2;

    int fw = (wid & 3) * 32, bw = (wid >> 2) * 32;
    float acc[2][4][4];
#pragma unroll
    for (int i = 0; i < 2; i++)
#pragma unroll
        for (int j = 0; j < 4; j++)
#pragma unroll
            for (int r = 0; r < 4; r++) acc[i][j][r] = 0.f;

    for (int kk = 0; kk < p.K; kk += 16) {
        float4 wv[2], av;
        if (p.trans) {
#pragma unroll
            for (int i = 0; i < 2; i++) {
                int idx = tid + 256 * i;
                int k = idx >> 5;                       // wid + 8i, 0..15
                wv[i] = *(const float4*)&Wp[(size_t)(kk + k) * p.ldW + f0 + 4 * lane];
            }
        } else {
#pragma unroll
            for (int i = 0; i < 2; i++) {
                int idx = tid + 256 * i;
                int f = idx >> 2, kq = (idx & 3) * 4;
                wv[i] = *(const float4*)&Wp[(size_t)(f0 + f) * p.ldW + kk + kq];
            }
        }
        {
            int b = tid >> 2, kq = (tid & 3) * 4;
            av = *(const float4*)&Ap[(size_t)b * p.ldA + kk + kq];
        }
        __syncthreads();
        if (p.trans) {
#pragma unroll
            for (int i = 0; i < 2; i++) {
                int idx = tid + 256 * i;
                int k = idx >> 5;
                float w4[4] = {wv[i].x, wv[i].y, wv[i].z, wv[i].w};
#pragma unroll
                for (int j = 0; j < 4; j++) {
                    int c = (j + lane) & 3;
                    uint32_t hi = t32(w4[c]);
                    Ah[(4 * lane + c) * 20 + k] = hi;
                    Al[(4 * lane + c) * 20 + k] = t32(w4[c] - __uint_as_float(hi));
                }
            }
        } else {
#pragma unroll
            for (int i = 0; i < 2; i++) {
                int idx = tid + 256 * i;
                int f = idx >> 2, kq = (idx & 3) * 4;
                float w4[4] = {wv[i].x, wv[i].y, wv[i].z, wv[i].w};
#pragma unroll
                for (int j = 0; j < 4; j++) {
                    uint32_t hi = t32(w4[j]);
                    Ah[f * 20 + kq + j] = hi;
                    Al[f * 20 + kq + j] = t32(w4[j] - __uint_as_float(hi));
                }
            }
        }
        {
            int b = tid >> 2, kq = (tid & 3) * 4;
            float a4[4] = {av.x, av.y, av.z, av.w};
#pragma unroll
            for (int j = 0; j < 4; j++) {
                uint32_t hi = t32(a4[j]);
                Bh[b * 20 + kq + j] = hi;
                Bl[b * 20 + kq + j] = t32(a4[j] - __uint_as_float(hi));
            }
        }
        __syncthreads();

#pragma unroll
        for (int s = 0; s < 2; s++) {
            uint32_t ah[2][4], al[2][4], bh[4][2], bl[4][2];
#pragma unroll
            for (int i = 0; i < 2; i++) {
                int fb = fw + 16 * i + tg;
                ah[i][0] = Ah[fb * 20 + 8 * s + tq];
                ah[i][1] = Ah[(fb + 8) * 20 + 8 * s + tq];
                ah[i][2] = Ah[fb * 20 + 8 * s + tq + 4];
                ah[i][3] = Ah[(fb + 8) * 20 + 8 * s + tq + 4];
                al[i][0] = Al[fb * 20 + 8 * s + tq];
                al[i][1] = Al[(fb + 8) * 20 + 8 * s + tq];
                al[i][2] = Al[fb * 20 + 8 * s + tq + 4];
                al[i][3] = Al[(fb + 8) * 20 + 8 * s + tq + 4];
            }
#pragma unroll
            for (int j = 0; j < 4; j++) {
                int nb = bw + 8 * j + tg;
                bh[j][0] = Bh[nb * 20 + 8 * s + tq];
                bh[j][1] = Bh[nb * 20 + 8 * s + tq + 4];
                bl[j][0] = Bl[nb * 20 + 8 * s + tq];
                bl[j][1] = Bl[nb * 20 + 8 * s + tq + 4];
            }
#pragma unroll
            for (int i = 0; i < 2; i++)
#pragma unroll
                for (int j = 0; j < 4; j++) {
                    mma8(acc[i][j], al[i], bh[j][0], bh[j][1]);
                    mma8(acc[i][j], ah[i], bl[j][0], bl[j][1]);
                    mma8(acc[i][j], ah[i], bh[j][0], bh[j][1]);
                }
        }
        __syncthreads();
    }

    const float* bp = (p.epi >= 1) ? bias + (size_t)z1 * p.sb1 + (size_t)z2 * p.sb2 : nullptr;
#pragma unroll
    for (int i = 0; i < 2; i++) {
        int fr = f0 + fw + 16 * i + tg, frh = fr + 8;
        float bv0 = bp ? bp[fr] : 0.f, bv1 = bp ? bp[frh] : 0.f;
#pragma unroll
        for (int j = 0; j < 4; j++) {
            int bc = bw + 8 * j + 2 * tq;
            float v0 = acc[i][j][0] + bv0, v1 = acc[i][j][1] + bv0;
            float v2 = acc[i][j][2] + bv1, v3 = acc[i][j][3] + bv1;
            if (p.epi == 2) {
                v0 = fmaxf(v0, 0.f); v1 = fmaxf(v1, 0.f);
                v2 = fmaxf(v2, 0.f); v3 = fmaxf(v3, 0.f);
            } else if (p.epi == 3) {
                v0 = tanhf(fmaxf(v0, 0.f)); v1 = tanhf(fmaxf(v1, 0.f));
                v2 = tanhf(fmaxf(v2, 0.f)); v3 = tanhf(fmaxf(v3, 0.f));
            }
            Cp[(size_t)bc * p.ldc + fr]        = v0;
            Cp[(size_t)(bc + 1) * p.ldc + fr]  = v1;
            Cp[(size_t)bc * p.ldc + frh]       = v2;
            Cp[(size_t)(bc + 1) * p.ldc + frh] = v3;
        }
    }
}

// ===================== fp32 SGEMM (K5 only) =====================
struct GP {
    int N, K, lda, ldb, ldc, n2, epi;
    int sA1, sA2, sB1, sB2, sC1, sC2, sb1, sb2;
    unsigned oA, oC;
};

__global__ __launch_bounds__(256) void gemm_nn(
    const float* __restrict__ Ain, const float* __restrict__ Bm,
    const float* __restrict__ bias, GP p)
{
    __shared__ float As[16][68];
    __shared__ float Bs[16][132];
    const float* A = Ain ? Ain : g_buf + p.oA;
    float*       C = g_buf + p.oC;
    int z = blockIdx.z, z1 = z / p.n2, z2 = z - z1 * p.n2;
    A  += (size_t)z1 * p.sA1 + (size_t)z2 * p.sA2;
    Bm += (size_t)z1 * p.sB1 + (size_t)z2 * p.sB2;
    C  += (size_t)z1 * p.sC1 + (size_t)z2 * p.sC2;
    int n0 = blockIdx.x * 128, tid = threadIdx.x, tx = tid & 15, ty = tid >> 4;
    float acc[4][8];
#pragma unroll
    for (int i = 0; i < 4; i++)
#pragma unroll
        for (int j = 0; j < 8; j++) acc[i][j] = 0.f;
    int a_row = tid >> 2, a_k4 = (tid & 3) * 4;
    for (int kk = 0; kk < p.K; kk += 16) {
        float4 av = *(const float4*)&A[a_row * (size_t)p.lda + kk + a_k4];
        float4 bv[2];
#pragma unroll
        for (int t = 0; t < 2; t++) {
            int idx = tid + 256 * t, bk = idx >> 5, bn4 = (idx & 31) * 4;
            bv[t] = (n0 + bn4 < p.N) ? *(const float4*)&Bm[(kk + bk) * (size_t)p.ldb + n0 + bn4]
                                     : make_float4(0.f, 0.f, 0.f, 0.f);
        }
        __syncthreads();
        As[a_k4 + 0][a_row] = av.x; As[a_k4 + 1][a_row] = av.y;
        As[a_k4 + 2][a_row] = av.z; As[a_k4 + 3][a_row] = av.w;
#pragma unroll
        for (int t = 0; t < 2; t++) {
            int idx = tid + 256 * t, bk = idx >> 5, bn4 = (idx & 31) * 4;
            *(float4*)&Bs[bk][bn4] = bv[t];
        }
        __syncthreads();
#pragma unroll
        for (int k = 0; k < 16; k++) {
            float4 af = *(const float4*)&As[k][ty << 2];
            float4 b0 = *(const float4*)&Bs[k][tx << 3];
            float4 b1 = *(const float4*)&Bs[k][(tx << 3) + 4];
            float ar[4] = {af.x, af.y, af.z, af.w};
            float br[8] = {b0.x, b0.y, b0.z, b0.w, b1.x, b1.y, b1.z, b1.w};
#pragma unroll
            for (int i = 0; i < 4; i++)
#pragma unroll
                for (int j = 0; j < 8; j++) acc[i][j] += ar[i] * br[j];
        }
    }
    const float* bp = bias ? bias + (size_t)z1 * p.sb1 + (size_t)z2 * p.sb2 : nullptr;
#pragma unroll
    for (int i = 0; i < 4; i++) {
        int r = (ty << 2) + i;
#pragma unroll
        for (int j = 0; j < 8; j++) {
            int c = n0 + (tx << 3) + j;
            if (c < p.N) {
                float v = acc[i][j];
                if (p.epi >= 1) v += bp[c];
                if (p.epi == 2) v = fmaxf(v, 0.f);
                C[r * (size_t)p.ldc + c] = v;
            }
        }
    }
}

// ===================== small kernels =====================
__global__ void softmax_k()
{
    float* sc = g_buf + O_SC;
    int row = blockIdx.x * 8 + (threadIdx.x >> 5), lane = threadIdx.x & 31;
    float4 v = *(float4*)&sc[(size_t)row * SS + lane * 4];
    float mx = fmaxf(fmaxf(v.x, v.y), fmaxf(v.z, v.w));
#pragma unroll
    for (int o = 16; o; o >>= 1) mx = fmaxf(mx, __shfl_xor_sync(0xffffffffu, mx, o));
    float4 e;
    e.x = __expf((v.x - mx) * 0.125f); e.y = __expf((v.y - mx) * 0.125f);
    e.z = __expf((v.z - mx) * 0.125f); e.w = __expf((v.w - mx) * 0.125f);
    float s = e.x + e.y + e.z + e.w;
#pragma unroll
    for (int o = 16; o; o >>= 1) s += __shfl_xor_sync(0xffffffffu, s, o);
    float inv = 1.f / s;
    e.x *= inv; e.y *= inv; e.z *= inv; e.w *= inv;
    *(float4*)&sc[(size_t)row * SS + lane * 4] = e;
}

__global__ void xfill_k(const float* __restrict__ prev_state)
{
    int idx = blockIdx.x * 256 + threadIdx.x;
    if (idx < MM * BB * DD) {
        int mb = idx / DD, j = idx - mb * DD;
        g_buf[O_X + (size_t)mb * (2 * DD) + DD + j] = fmaxf(prev_state[idx], 0.f);
    }
}

__global__ void gate_k(const float* __restrict__ Wg2, const float* __restrict__ bg2)
{
    int row = blockIdx.x * 8 + (threadIdx.x >> 5), lane = threadIdx.x & 31;
    int gm = row / BB;
    const float* hg = g_buf + O_HG + (size_t)row * FF;
    const float* w  = &Wg2[(size_t)gm * FF];
    float s = 0.f;
#pragma unroll
    for (int f = lane * 4; f < FF; f += 128) {
        float4 a = *(const float4*)&hg[f];
        float4 b = *(const float4*)&w[f];
        s += a.x * b.x + a.y * b.y + a.z * b.z + a.w * b.w;
    }
#pragma unroll
    for (int o = 16; o; o >>= 1) s += __shfl_xor_sync(0xffffffffu, s, o);
    if (lane == 0)
        g_buf[O_GT + row] = 1.f / (1.f + __expf(-(s + bg2[gm])));
}

__global__ void final_k(const float* __restrict__ pq, const float* __restrict__ pk,
                        const float* __restrict__ pv, const float* __restrict__ ps,
                        float* __restrict__ out)
{
    int idx = blockIdx.x * 256 + threadIdx.x;
    int o = idx / (MM * BB * DD);
    int rem = idx - o * (MM * BB * DD);
    int mb = rem / DD;
    int g = (o == 0) ? 3 : (o - 1);
    const float* prev = (o == 0) ? ps : (o == 1) ? pq : (o == 2) ? pk : pv;
    float gt = g_buf[O_GT + g * MM * BB + mb];
    float ov = g_buf[O_OB + (size_t)g * MM * BB * DD + rem];
    out[idx] = gt * ov + (1.f - gt) * prev[rem];
}

// ===================== launch =====================
static TGP mkT(int K, int ldW, int ldA, int ldc, int n2, int trans, int epi,
               int sW1, int sW2, int sA1, int sA2, int sC1, int sC2, int sb1, int sb2,
               unsigned oW, unsigned oA, unsigned oC)
{
    TGP p; p.K = K; p.ldW = ldW; p.ldA = ldA; p.ldc = ldc; p.n2 = n2; p.trans = trans; p.epi = epi;
    p.sW1 = sW1; p.sW2 = sW2; p.sA1 = sA1; p.sA2 = sA2; p.sC1 = sC1; p.sC2 = sC2;
    p.sb1 = sb1; p.sb2 = sb2; p.oW = oW; p.oA = oA; p.oC = oC;
    return p;
}
static GP mk(int N, int K, int lda, int ldb, int ldc, int n2, int epi,
             int sA1, int sA2, int sB1, int sB2, int sC1, int sC2, int sb1, int sb2,
             unsigned oA, unsigned oC)
{
    GP p; p.N = N; p.K = K; p.lda = lda; p.ldb = ldb; p.ldc = ldc; p.n2 = n2; p.epi = epi;
    p.sA1 = sA1; p.sA2 = sA2; p.sB1 = sB1; p.sB2 = sB2; p.sC1 = sC1; p.sC2 = sC2;
    p.sb1 = sb1; p.sb2 = sb2; p.oA = oA; p.oC = oC;
    return p;
}

extern "C" void kernel_launch(void* const* d_in, const int* in_sizes, int n_in,
                              void* d_out, int out_size)
{
    const float* prev_state = (const float*)d_in[0];
    const float* prev_query = (const float*)d_in[1];
    const float* prev_key   = (const float*)d_in[2];
    const float* prev_value = (const float*)d_in[3];
    const float* key_in     = (const float*)d_in[4];
    const float* value_in   = (const float*)d_in[5];
    const float* Wq  = (const float*)d_in[6];
    const float* bq  = (const float*)d_in[7];
    const float* Wk  = (const float*)d_in[8];
    // bk (d_in[9]) dead: constant over s -> softmax-invariant
    const float* Wv  = (const float*)d_in[10];
    const float* bv  = (const float*)d_in[11];
    const float* Wo  = (const float*)d_in[12];
    const float* bo  = (const float*)d_in[13];
    const float* W1  = (const float*)d_in[14];
    const float* b1  = (const float*)d_in[15];
    const float* W2  = (const float*)d_in[16];
    const float* b2  = (const float*)d_in[17];
    const float* Wg1 = (const float*)d_in[18];
    const float* bg1 = (const float*)d_in[19];
    const float* Wg2 = (const float*)d_in[20];
    const float* bg2 = (const float*)d_in[21];

    // K1: q[m][b,f] = prev_query[m] @ Wq[m] + bq     (split, trans, K=512)
    mma_gemm3<<<dim3(4, 1, MM), 256>>>(Wq, prev_query, bq,
        mkT(DD, DD, DD, DD, 1, 1, 1,  DD*DD,0,  BB*DD,0,  BB*DD,0,  DD,0,  0,0, O_Q));

    // K2: tq[b][mh][kin] = sum_j q[m][b,h64+j]*Wk[m][kin][h64+j]  (split, no-trans, K=64)
    mma_gemm3<<<dim3(4, 1, MM*HH), 256>>>(Wk, nullptr, nullptr,
        mkT(HD, DD, DD, MH*DD, HH, 0, 0,  DD*DD,HD,  BB*DD,HD,  HH*DD,DD,  0,0,  0, O_Q, O_TQ));

    // K3: sc[b][mh][s] = key_in[s,b,:] . tq[b][mh,:]  (split, no-trans, K=512, f=s)
    mma_gemm3<<<dim3(1, 1, BB), 256>>>(key_in, nullptr, nullptr,
        mkT(DD, BB*DD, DD, SS, 1, 0, 0,  DD,0,  MH*DD,0,  MH*SS,0,  0,0,  0, O_TQ, O_SC));

    softmax_k<<<BB*MH/8, 256>>>();

    // K4: u[b][mh][k] = sum_s w[b][mh,s]*value_in[s,b,k]  (split, trans, K=128, f=k)
    mma_gemm3<<<dim3(4, 1, BB), 256>>>(value_in, nullptr, nullptr,
        mkT(SS, BB*DD, SS, DD, 1, 1, 0,  DD,0,  MH*SS,0,  MH*DD,0,  0,0,  0, O_SC, O_U));

    // K5 (fp32): ao[m][b,h64+j] = sum_k u[b][mh,k]*Wv[m][k,h64+j] + bv
    gemm_nn<<<dim3(1, 1, MM*HH), 256>>>(nullptr, Wv, bv,
        mk(HD, DD, MH*DD, DD, DD, HH, 1,  HH*DD,DD,  DD*DD,HD,  BB*DD,HD,  DD,HD,  O_U, O_AO));

    // K6: x[:, :D] = relu(ao @ Wo + bo)               (split, trans, K=512)
    mma_gemm3<<<dim3(4, 1, MM), 256>>>(Wo, nullptr, bo,
        mkT(DD, DD, DD, 2*DD, 1, 1, 2,  DD*DD,0,  BB*DD,0,  BB*2*DD,0,  DD,0,  0, O_AO, O_X));

    xfill_k<<<(MM*BB*DD)/256, 256>>>(prev_state);

    // K7a: h = relu(x @ W1 + b1)                      (single tf32, trans, K=1024)
    mma_gemm1<<<dim3(8, 1, GG*MM), 256>>>(W1, nullptr, b1,
        mkT(2*DD, FF, 2*DD, FF, MM, 1, 2,
            MM*2*DD*FF, 2*DD*FF,  0, BB*2*DD,  MM*BB*FF, BB*FF,  MM*FF, FF,  0, O_X, O_H));

    // K7b: hg = relu(x @ Wg1 + bg1)
    mma_gemm1<<<dim3(8, 1, GG*MM), 256>>>(Wg1, nullptr, bg1,
        mkT(2*DD, FF, 2*DD, FF, MM, 1, 2,
            MM*2*DD*FF, 2*DD*FF,  0, BB*2*DD,  MM*BB*FF, BB*FF,  MM*FF, FF,  0, O_X, O_HG));

    // K8a: ob = tanh(relu(h @ W2 + b2))               (single tf32, trans, K=1024)
    mma_gemm1<<<dim3(4, 1, GG*MM), 256>>>(W2, nullptr, b2,
        mkT(FF, DD, FF, DD, MM, 1, 3,
            MM*FF*DD, FF*DD,  MM*BB*FF, BB*FF,  MM*BB*DD, BB*DD,  MM*DD, DD,  0, O_H, O_OB));

    gate_k<<<GG*MM*BB/8, 256>>>(Wg2, bg2);

    final_k<<<(GG*MM*BB*DD)/256, 256>>>(prev_query, prev_key, prev_value, prev_state,
                                        (float*)d_out);
}

// round 8
// speedup vs baseline: 1.9977x; 1.0604x over previous
#include <cuda_runtime.h>
#include <math.h>
#include <stdint.h>

#define MM 8
#define BB 64
#define SS 128
#define DD 512
#define HH 8
#define FF 1024
#define HD 64
#define MH 64
#define GG 4

#define O_Q   0u
#define O_TQ  262144u
#define O_SC  2359296u
#define O_U   2883584u
#define O_AO  4980736u
#define O_X   5242880u
#define O_H   5767168u
#define O_HG  7864320u
#define O_OB  9961472u
#define O_GT  11010048u
#define SCRATCH_ELEMS 11012096u

__device__ float g_buf[SCRATCH_ELEMS];

// ===================== helpers =====================
__device__ __forceinline__ uint32_t t32(float x) {
    uint32_t r;
    asm("cvt.rna.tf32.f32 %0, %1;" : "=r"(r) : "f"(x));
    return r;
}

__device__ __forceinline__ void mma8(float* c, const uint32_t* a, uint32_t b0, uint32_t b1) {
    asm volatile("mma.sync.aligned.m16n8k8.row.col.f32.tf32.tf32.f32 "
        "{%0,%1,%2,%3}, {%4,%5,%6,%7}, {%8,%9}, {%0,%1,%2,%3};"
        : "+f"(c[0]), "+f"(c[1]), "+f"(c[2]), "+f"(c[3])
        : "r"(a[0]), "r"(a[1]), "r"(a[2]), "r"(a[3]), "r"(b0), "r"(b1));
}

// D[f,b] = sum_k W[f,k]*A[b,k]; C[b*ldc+f]
// trans=1: W gmem [k][f]; trans=0: W gmem [f][k].
// epi: 0 none, 1 +bias, 2 relu+bias, 3 tanh(relu+bias)
struct TGP {
    int K, ldW, ldA, ldc, n2, trans, epi;
    int sW1, sW2, sA1, sA2, sC1, sC2, sb1, sb2;
    unsigned oW, oA, oC;
};

// ===================== single-product tf32 GEMM (K-tile 32, double-buffered) ==
#define G1A 4608u                  // 128*36 words per A stage
#define G1B 2304u                  // 64*36 words per B stage
#define G1_SMEM ((G1A + G1B) * 2u * 4u)   // 55296 B

__global__ __launch_bounds__(256) void mma_gemm1(
    const float* __restrict__ Wg, const float* __restrict__ Ag,
    const float* __restrict__ bias, TGP p)
{
    extern __shared__ uint32_t sm1[];
    uint32_t* AsB[2] = {sm1, sm1 + G1A};
    uint32_t* BsB[2] = {sm1 + 2u * G1A, sm1 + 2u * G1A + G1B};

    int tid = threadIdx.x, wid = tid >> 5, lane = tid & 31;
    int tg = lane >> 2, tq = lane & 3;
    int z = blockIdx.z, z1 = z / p.n2, z2 = z - z1 * p.n2;
    int f0 = blockIdx.x * 128;

    const float* Wp = (Wg ? Wg : g_buf + p.oW) + (size_t)z1 * p.sW1 + (size_t)z2 * p.sW2;
    const float* Ap = (Ag ? Ag : g_buf + p.oA) + (size_t)z1 * p.sA1 + (size_t)z2 * p.sA2;
    float*       Cp = g_buf + p.oC + (size_t)z1 * p.sC1 + (size_t)z2 * p.sC2;

    int fw = (wid & 3) * 32, bw = (wid >> 2) * 32;
    float acc[2][4][4];
#pragma unroll
    for (int i = 0; i < 2; i++)
#pragma unroll
        for (int j = 0; j < 4; j++)
#pragma unroll
            for (int r = 0; r < 4; r++) acc[i][j][r] = 0.f;

    float4 wv[4], av[2];

    auto LDG = [&](int kk) {
        if (p.trans) {
#pragma unroll
            for (int i = 0; i < 4; i++) {
                int k = (tid >> 5) + 8 * i;
                wv[i] = *(const float4*)&Wp[(size_t)(kk + k) * p.ldW + f0 + 4 * lane];
            }
        } else {
#pragma unroll
            for (int i = 0; i < 4; i++) {
                int idx = tid + 256 * i;
                int f = idx >> 3, kq = (idx & 7) * 4;
                wv[i] = *(const float4*)&Wp[(size_t)(f0 + f) * p.ldW + kk + kq];
            }
        }
#pragma unroll
        for (int i = 0; i < 2; i++) {
            int idx = tid + 256 * i;
            int b = idx >> 3, kq = (idx & 7) * 4;
            av[i] = *(const float4*)&Ap[(size_t)b * p.ldA + kk + kq];
        }
    };

    auto STS = [&](uint32_t* As, uint32_t* Bs) {
        if (p.trans) {
#pragma unroll
            for (int i = 0; i < 4; i++) {
                int k = (tid >> 5) + 8 * i;
                float w4[4] = {wv[i].x, wv[i].y, wv[i].z, wv[i].w};
#pragma unroll
                for (int j = 0; j < 4; j++) {
                    int c = (j + lane) & 3;
                    As[(4 * lane + c) * 36 + k] = t32(w4[c]);
                }
            }
        } else {
#pragma unroll
            for (int i = 0; i < 4; i++) {
                int idx = tid + 256 * i;
                int f = idx >> 3, kq = (idx & 7) * 4;
                As[f * 36 + kq + 0] = t32(wv[i].x);
                As[f * 36 + kq + 1] = t32(wv[i].y);
                As[f * 36 + kq + 2] = t32(wv[i].z);
                As[f * 36 + kq + 3] = t32(wv[i].w);
            }
        }
#pragma unroll
        for (int i = 0; i < 2; i++) {
            int idx = tid + 256 * i;
            int b = idx >> 3, kq = (idx & 7) * 4;
            Bs[b * 36 + kq + 0] = t32(av[i].x);
            Bs[b * 36 + kq + 1] = t32(av[i].y);
            Bs[b * 36 + kq + 2] = t32(av[i].z);
            Bs[b * 36 + kq + 3] = t32(av[i].w);
        }
    };

    auto CMP = [&](const uint32_t* As, const uint32_t* Bs) {
#pragma unroll
        for (int s = 0; s < 4; s++) {
            uint32_t a[2][4], bq[4][2];
#pragma unroll
            for (int i = 0; i < 2; i++) {
                int fb = fw + 16 * i + tg;
                a[i][0] = As[fb * 36 + 8 * s + tq];
                a[i][1] = As[(fb + 8) * 36 + 8 * s + tq];
                a[i][2] = As[fb * 36 + 8 * s + tq + 4];
                a[i][3] = As[(fb + 8) * 36 + 8 * s + tq + 4];
            }
#pragma unroll
            for (int j = 0; j < 4; j++) {
                int nb = bw + 8 * j + tg;
                bq[j][0] = Bs[nb * 36 + 8 * s + tq];
                bq[j][1] = Bs[nb * 36 + 8 * s + tq + 4];
            }
#pragma unroll
            for (int i = 0; i < 2; i++)
#pragma unroll
                for (int j = 0; j < 4; j++)
                    mma8(acc[i][j], a[i], bq[j][0], bq[j][1]);
        }
    };

    int nt = p.K >> 5;
    LDG(0);
    STS(AsB[0], BsB[0]);
    __syncthreads();
    for (int t = 0; t < nt; t++) {
        if (t + 1 < nt) LDG((t + 1) << 5);
        CMP(AsB[t & 1], BsB[t & 1]);
        if (t + 1 < nt) STS(AsB[(t + 1) & 1], BsB[(t + 1) & 1]);
        __syncthreads();
    }

    const float* bp = (p.epi >= 1) ? bias + (size_t)z1 * p.sb1 + (size_t)z2 * p.sb2 : nullptr;
#pragma unroll
    for (int i = 0; i < 2; i++) {
        int fr = f0 + fw + 16 * i + tg, frh = fr + 8;
        float bv0 = bp ? bp[fr] : 0.f, bv1 = bp ? bp[frh] : 0.f;
#pragma unroll
        for (int j = 0; j < 4; j++) {
            int bc = bw + 8 * j + 2 * tq;
            float v0 = acc[i][j][0] + bv0, v1 = acc[i][j][1] + bv0;
            float v2 = acc[i][j][2] + bv1, v3 = acc[i][j][3] + bv1;
            if (p.epi == 2) {
                v0 = fmaxf(v0, 0.f); v1 = fmaxf(v1, 0.f);
                v2 = fmaxf(v2, 0.f); v3 = fmaxf(v3, 0.f);
            } else if (p.epi == 3) {
                v0 = tanhf(fmaxf(v0, 0.f)); v1 = tanhf(fmaxf(v1, 0.f));
                v2 = tanhf(fmaxf(v2, 0.f)); v3 = tanhf(fmaxf(v3, 0.f));
            }
            Cp[(size_t)bc * p.ldc + fr]        = v0;
            Cp[(size_t)(bc + 1) * p.ldc + fr]  = v1;
            Cp[(size_t)bc * p.ldc + frh]       = v2;
            Cp[(size_t)(bc + 1) * p.ldc + frh] = v3;
        }
    }
}

// ===================== 3xTF32 split GEMM (K-tile 16, double-buffered) =========
#define G3A 2560u                  // 128*20 words per (Ah|Al) stage
#define G3B 1280u                  // 64*20 words per (Bh|Bl) stage
#define G3_STAGE (2u * G3A + 2u * G3B)
#define G3_SMEM (G3_STAGE * 2u * 4u)      // 61440 B

__global__ __launch_bounds__(256) void mma_gemm3(
    const float* __restrict__ Wg, const float* __restrict__ Ag,
    const float* __restrict__ bias, TGP p)
{
    extern __shared__ uint32_t sm3[];

    int tid = threadIdx.x, wid = tid >> 5, lane = tid & 31;
    int tg = lane >> 2, tq = lane & 3;
    int z = blockIdx.z, z1 = z / p.n2, z2 = z - z1 * p.n2;
    int f0 = blockIdx.x * 128;

    const float* Wp = (Wg ? Wg : g_buf + p.oW) + (size_t)z1 * p.sW1 + (size_t)z2 * p.sW2;
    const float* Ap = (Ag ? Ag : g_buf + p.oA) + (size_t)z1 * p.sA1 + (size_t)z2 * p.sA2;
    float*       Cp = g_buf + p.oC + (size_t)z1 * p.sC1 + (size_t)z2 * p.sC2;

    int fw = (wid & 3) * 32, bw = (wid >> 2) * 32;
    float acc[2][4][4];
#pragma unroll
    for (int i = 0; i < 2; i++)
#pragma unroll
        for (int j = 0; j < 4; j++)
#pragma unroll
            for (int r = 0; r < 4; r++) acc[i][j][r] = 0.f;

    float4 wv[2], av;

    auto LDG = [&](int kk) {
        if (p.trans) {
#pragma unroll
            for (int i = 0; i < 2; i++) {
                int k = (tid >> 5) + 8 * i;
                wv[i] = *(const float4*)&Wp[(size_t)(kk + k) * p.ldW + f0 + 4 * lane];
            }
        } else {
#pragma unroll
            for (int i = 0; i < 2; i++) {
                int idx = tid + 256 * i;
                int f = idx >> 2, kq = (idx & 3) * 4;
                wv[i] = *(const float4*)&Wp[(size_t)(f0 + f) * p.ldW + kk + kq];
            }
        }
        {
            int b = tid >> 2, kq = (tid & 3) * 4;
            av = *(const float4*)&Ap[(size_t)b * p.ldA + kk + kq];
        }
    };

    auto STS = [&](uint32_t* base) {
        uint32_t* Ah = base;
        uint32_t* Al = base + G3A;
        uint32_t* Bh = base + 2u * G3A;
        uint32_t* Bl = base + 2u * G3A + G3B;
        if (p.trans) {
#pragma unroll
            for (int i = 0; i < 2; i++) {
                int k = (tid >> 5) + 8 * i;
                float w4[4] = {wv[i].x, wv[i].y, wv[i].z, wv[i].w};
#pragma unroll
                for (int j = 0; j < 4; j++) {
                    int c = (j + lane) & 3;
                    uint32_t hi = t32(w4[c]);
                    Ah[(4 * lane + c) * 20 + k] = hi;
                    Al[(4 * lane + c) * 20 + k] = t32(w4[c] - __uint_as_float(hi));
                }
            }
        } else {
#pragma unroll
            for (int i = 0; i < 2; i++) {
                int idx = tid + 256 * i;
                int f = idx >> 2, kq = (idx & 3) * 4;
                float w4[4] = {wv[i].x, wv[i].y, wv[i].z, wv[i].w};
#pragma unroll
                for (int j = 0; j < 4; j++) {
                    uint32_t hi = t32(w4[j]);
                    Ah[f * 20 + kq + j] = hi;
                    Al[f * 20 + kq + j] = t32(w4[j] - __uint_as_float(hi));
                }
            }
        }
        {
            int b = tid >> 2, kq = (tid & 3) * 4;
            float a4[4] = {av.x, av.y, av.z, av.w};
#pragma unroll
            for (int j = 0; j < 4; j++) {
                uint32_t hi = t32(a4[j]);
                Bh[b * 20 + kq + j] = hi;
                Bl[b * 20 + kq + j] = t32(a4[j] - __uint_as_float(hi));
            }
        }
    };

    auto CMP = [&](const uint32_t* base) {
        const uint32_t* Ah = base;
        const uint32_t* Al = base + G3A;
        const uint32_t* Bh = base + 2u * G3A;
        const uint32_t* Bl = base + 2u * G3A + G3B;
#pragma unroll
        for (int s = 0; s < 2; s++) {
            uint32_t ah[2][4], al[2][4], bh[4][2], bl[4][2];
#pragma unroll
            for (int i = 0; i < 2; i++) {
                int fb = fw + 16 * i + tg;
                ah[i][0] = Ah[fb * 20 + 8 * s + tq];
                ah[i][1] = Ah[(fb + 8) * 20 + 8 * s + tq];
                ah[i][2] = Ah[fb * 20 + 8 * s + tq + 4];
                ah[i][3] = Ah[(fb + 8) * 20 + 8 * s + tq + 4];
                al[i][0] = Al[fb * 20 + 8 * s + tq];
                al[i][1] = Al[(fb + 8) * 20 + 8 * s + tq];
                al[i][2] = Al[fb * 20 + 8 * s + tq + 4];
                al[i][3] = Al[(fb + 8) * 20 + 8 * s + tq + 4];
            }
#pragma unroll
            for (int j = 0; j < 4; j++) {
                int nb = bw + 8 * j + tg;
                bh[j][0] = Bh[nb * 20 + 8 * s + tq];
                bh[j][1] = Bh[nb * 20 + 8 * s + tq + 4];
                bl[j][0] = Bl[nb * 20 + 8 * s + tq];
                bl[j][1] = Bl[nb * 20 + 8 * s + tq + 4];
            }
#pragma unroll
            for (int i = 0; i < 2; i++)
#pragma unroll
                for (int j = 0; j < 4; j++) {
                    mma8(acc[i][j], al[i], bh[j][0], bh[j][1]);
                    mma8(acc[i][j], ah[i], bl[j][0], bl[j][1]);
                    mma8(acc[i][j], ah[i], bh[j][0], bh[j][1]);
                }
        }
    };

    int nt = p.K >> 4;
    LDG(0);
    STS(sm3);
    __syncthreads();
    for (int t = 0; t < nt; t++) {
        if (t + 1 < nt) LDG((t + 1) << 4);
        CMP(sm3 + (t & 1) * G3_STAGE);
        if (t + 1 < nt) STS(sm3 + ((t + 1) & 1) * G3_STAGE);
        __syncthreads();
    }

    const float* bp = (p.epi >= 1) ? bias + (size_t)z1 * p.sb1 + (size_t)z2 * p.sb2 : nullptr;
#pragma unroll
    for (int i = 0; i < 2; i++) {
        int fr = f0 + fw + 16 * i + tg, frh = fr + 8;
        float bv0 = bp ? bp[fr] : 0.f, bv1 = bp ? bp[frh] : 0.f;
#pragma unroll
        for (int j = 0; j < 4; j++) {
            int bc = bw + 8 * j + 2 * tq;
            float v0 = acc[i][j][0] + bv0, v1 = acc[i][j][1] + bv0;
            float v2 = acc[i][j][2] + bv1, v3 = acc[i][j][3] + bv1;
            if (p.epi == 2) {
                v0 = fmaxf(v0, 0.f); v1 = fmaxf(v1, 0.f);
                v2 = fmaxf(v2, 0.f); v3 = fmaxf(v3, 0.f);
            } else if (p.epi == 3) {
                v0 = tanhf(fmaxf(v0, 0.f)); v1 = tanhf(fmaxf(v1, 0.f));
                v2 = tanhf(fmaxf(v2, 0.f)); v3 = tanhf(fmaxf(v3, 0.f));
            }
            Cp[(size_t)bc * p.ldc + fr]        = v0;
            Cp[(size_t)(bc + 1) * p.ldc + fr]  = v1;
            Cp[(size_t)bc * p.ldc + frh]       = v2;
            Cp[(size_t)(bc + 1) * p.ldc + frh] = v3;
        }
    }
}

// ===================== fp32 SGEMM (K5 only) =====================
struct GP {
    int N, K, lda, ldb, ldc, n2, epi;
    int sA1, sA2, sB1, sB2, sC1, sC2, sb1, sb2;
    unsigned oA, oC;
};

__global__ __launch_bounds__(256) void gemm_nn(
    const float* __restrict__ Ain, const float* __restrict__ Bm,
    const float* __restrict__ bias, GP p)
{
    __shared__ float As[16][68];
    __shared__ float Bs[16][132];
    const float* A = Ain ? Ain : g_buf + p.oA;
    float*       C = g_buf + p.oC;
    int z = blockIdx.z, z1 = z / p.n2, z2 = z - z1 * p.n2;
    A  += (size_t)z1 * p.sA1 + (size_t)z2 * p.sA2;
    Bm += (size_t)z1 * p.sB1 + (size_t)z2 * p.sB2;
    C  += (size_t)z1 * p.sC1 + (size_t)z2 * p.sC2;
    int n0 = blockIdx.x * 128, tid = threadIdx.x, tx = tid & 15, ty = tid >> 4;
    float acc[4][8];
#pragma unroll
    for (int i = 0; i < 4; i++)
#pragma unroll
        for (int j = 0; j < 8; j++) acc[i][j] = 0.f;
    int a_row = tid >> 2, a_k4 = (tid & 3) * 4;
    for (int kk = 0; kk < p.K; kk += 16) {
        float4 av = *(const float4*)&A[a_row * (size_t)p.lda + kk + a_k4];
        float4 bv[2];
#pragma unroll
        for (int t = 0; t < 2; t++) {
            int idx = tid + 256 * t, bk = idx >> 5, bn4 = (idx & 31) * 4;
            bv[t] = (n0 + bn4 < p.N) ? *(const float4*)&Bm[(kk + bk) * (size_t)p.ldb + n0 + bn4]
                                     : make_float4(0.f, 0.f, 0.f, 0.f);
        }
        __syncthreads();
        As[a_k4 + 0][a_row] = av.x; As[a_k4 + 1][a_row] = av.y;
        As[a_k4 + 2][a_row] = av.z; As[a_k4 + 3][a_row] = av.w;
#pragma unroll
        for (int t = 0; t < 2; t++) {
            int idx = tid + 256 * t, bk = idx >> 5, bn4 = (idx & 31) * 4;
            *(float4*)&Bs[bk][bn4] = bv[t];
        }
        __syncthreads();
#pragma unroll
        for (int k = 0; k < 16; k++) {
            float4 af = *(const float4*)&As[k][ty << 2];
            float4 b0 = *(const float4*)&Bs[k][tx << 3];
            float4 b1 = *(const float4*)&Bs[k][(tx << 3) + 4];
            float ar[4] = {af.x, af.y, af.z, af.w};
            float br[8] = {b0.x, b0.y, b0.z, b0.w, b1.x, b1.y, b1.z, b1.w};
#pragma unroll
            for (int i = 0; i < 4; i++)
#pragma unroll
                for (int j = 0; j < 8; j++) acc[i][j] += ar[i] * br[j];
        }
    }
    const float* bp = bias ? bias + (size_t)z1 * p.sb1 + (size_t)z2 * p.sb2 : nullptr;
#pragma unroll
    for (int i = 0; i < 4; i++) {
        int r = (ty << 2) + i;
#pragma unroll
        for (int j = 0; j < 8; j++) {
            int c = n0 + (tx << 3) + j;
            if (c < p.N) {
                float v = acc[i][j];
                if (p.epi >= 1) v += bp[c];
                if (p.epi == 2) v = fmaxf(v, 0.f);
                C[r * (size_t)p.ldc + c] = v;
            }
        }
    }
}

// ===================== small kernels =====================
__global__ void softmax_k()
{
    float* sc = g_buf + O_SC;
    int row = blockIdx.x * 8 + (threadIdx.x >> 5), lane = threadIdx.x & 31;
    float4 v = *(float4*)&sc[(size_t)row * SS + lane * 4];
    float mx = fmaxf(fmaxf(v.x, v.y), fmaxf(v.z, v.w));
#pragma unroll
    for (int o = 16; o; o >>= 1) mx = fmaxf(mx, __shfl_xor_sync(0xffffffffu, mx, o));
    float4 e;
    e.x = __expf((v.x - mx) * 0.125f); e.y = __expf((v.y - mx) * 0.125f);
    e.z = __expf((v.z - mx) * 0.125f); e.w = __expf((v.w - mx) * 0.125f);
    float s = e.x + e.y + e.z + e.w;
#pragma unroll
    for (int o = 16; o; o >>= 1) s += __shfl_xor_sync(0xffffffffu, s, o);
    float inv = 1.f / s;
    e.x *= inv; e.y *= inv; e.z *= inv; e.w *= inv;
    *(float4*)&sc[(size_t)row * SS + lane * 4] = e;
}

__global__ void xfill_k(const float* __restrict__ prev_state)
{
    int idx = blockIdx.x * 256 + threadIdx.x;
    if (idx < MM * BB * DD) {
        int mb = idx / DD, j = idx - mb * DD;
        g_buf[O_X + (size_t)mb * (2 * DD) + DD + j] = fmaxf(prev_state[idx], 0.f);
    }
}

__global__ void gate_k(const float* __restrict__ Wg2, const float* __restrict__ bg2)
{
    int row = blockIdx.x * 8 + (threadIdx.x >> 5), lane = threadIdx.x & 31;
    int gm = row / BB;
    const float* hg = g_buf + O_HG + (size_t)row * FF;
    const float* w  = &Wg2[(size_t)gm * FF];
    float s = 0.f;
#pragma unroll
    for (int f = lane * 4; f < FF; f += 128) {
        float4 a = *(const float4*)&hg[f];
        float4 b = *(const float4*)&w[f];
        s += a.x * b.x + a.y * b.y + a.z * b.z + a.w * b.w;
    }
#pragma unroll
    for (int o = 16; o; o >>= 1) s += __shfl_xor_sync(0xffffffffu, s, o);
    if (lane == 0)
        g_buf[O_GT + row] = 1.f / (1.f + __expf(-(s + bg2[gm])));
}

__global__ void final_k(const float* __restrict__ pq, const float* __restrict__ pk,
                        const float* __restrict__ pv, const float* __restrict__ ps,
                        float* __restrict__ out)
{
    int idx = blockIdx.x * 256 + threadIdx.x;
    int o = idx / (MM * BB * DD);
    int rem = idx - o * (MM * BB * DD);
    int mb = rem / DD;
    int g = (o == 0) ? 3 : (o - 1);
    const float* prev = (o == 0) ? ps : (o == 1) ? pq : (o == 2) ? pk : pv;
    float gt = g_buf[O_GT + g * MM * BB + mb];
    float ov = g_buf[O_OB + (size_t)g * MM * BB * DD + rem];
    out[idx] = gt * ov + (1.f - gt) * prev[rem];
}

// ===================== launch =====================
static TGP mkT(int K, int ldW, int ldA, int ldc, int n2, int trans, int epi,
               int sW1, int sW2, int sA1, int sA2, int sC1, int sC2, int sb1, int sb2,
               unsigned oW, unsigned oA, unsigned oC)
{
    TGP p; p.K = K; p.ldW = ldW; p.ldA = ldA; p.ldc = ldc; p.n2 = n2; p.trans = trans; p.epi = epi;
    p.sW1 = sW1; p.sW2 = sW2; p.sA1 = sA1; p.sA2 = sA2; p.sC1 = sC1; p.sC2 = sC2;
    p.sb1 = sb1; p.sb2 = sb2; p.oW = oW; p.oA = oA; p.oC = oC;
    return p;
}
static GP mk(int N, int K, int lda, int ldb, int ldc, int n2, int epi,
             int sA1, int sA2, int sB1, int sB2, int sC1, int sC2, int sb1, int sb2,
             unsigned oA, unsigned oC)
{
    GP p; p.N = N; p.K = K; p.lda = lda; p.ldb = ldb; p.ldc = ldc; p.n2 = n2; p.epi = epi;
    p.sA1 = sA1; p.sA2 = sA2; p.sB1 = sB1; p.sB2 = sB2; p.sC1 = sC1; p.sC2 = sC2;
    p.sb1 = sb1; p.sb2 = sb2; p.oA = oA; p.oC = oC;
    return p;
}

extern "C" void kernel_launch(void* const* d_in, const int* in_sizes, int n_in,
                              void* d_out, int out_size)
{
    const float* prev_state = (const float*)d_in[0];
    const float* prev_query = (const float*)d_in[1];
    const float* prev_key   = (const float*)d_in[2];
    const float* prev_value = (const float*)d_in[3];
    const float* key_in     = (const float*)d_in[4];
    const float* value_in   = (const float*)d_in[5];
    const float* Wq  = (const float*)d_in[6];
    const float* bq  = (const float*)d_in[7];
    const float* Wk  = (const float*)d_in[8];
    // bk (d_in[9]) dead: constant over s -> softmax-invariant
    const float* Wv  = (const float*)d_in[10];
    const float* bv  = (const float*)d_in[11];
    const float* Wo  = (const float*)d_in[12];
    const float* bo  = (const float*)d_in[13];
    const float* W1  = (const float*)d_in[14];
    const float* b1  = (const float*)d_in[15];
    const float* W2  = (const float*)d_in[16];
    const float* b2  = (const float*)d_in[17];
    const float* Wg1 = (const float*)d_in[18];
    const float* bg1 = (const float*)d_in[19];
    const float* Wg2 = (const float*)d_in[20];
    const float* bg2 = (const float*)d_in[21];

    cudaFuncSetAttribute(mma_gemm1, cudaFuncAttributeMaxDynamicSharedMemorySize, G1_SMEM);
    cudaFuncSetAttribute(mma_gemm3, cudaFuncAttributeMaxDynamicSharedMemorySize, G3_SMEM);

    // K1: q[m][b,f] = prev_query[m] @ Wq[m] + bq     (split, trans, K=512)
    mma_gemm3<<<dim3(4, 1, MM), 256, G3_SMEM>>>(Wq, prev_query, bq,
        mkT(DD, DD, DD, DD, 1, 1, 1,  DD*DD,0,  BB*DD,0,  BB*DD,0,  DD,0,  0,0, O_Q));

    // K2: tq[b][mh][kin] = sum_j q[m][b,h64+j]*Wk[m][kin][h64+j]  (split, no-trans, K=64)
    mma_gemm3<<<dim3(4, 1, MM*HH), 256, G3_SMEM>>>(Wk, nullptr, nullptr,
        mkT(HD, DD, DD, MH*DD, HH, 0, 0,  DD*DD,HD,  BB*DD,HD,  HH*DD,DD,  0,0,  0, O_Q, O_TQ));

    // K3: sc[b][mh][s] = key_in[s,b,:] . tq[b][mh,:]  (split, no-trans, K=512, f=s)
    mma_gemm3<<<dim3(1, 1, BB), 256, G3_SMEM>>>(key_in, nullptr, nullptr,
        mkT(DD, BB*DD, DD, SS, 1, 0, 0,  DD,0,  MH*DD,0,  MH*SS,0,  0,0,  0, O_TQ, O_SC));

    softmax_k<<<BB*MH/8, 256>>>();

    // K4: u[b][mh][k] = sum_s w[b][mh,s]*value_in[s,b,k]  (single tf32, trans, K=128)
    mma_gemm1<<<dim3(4, 1, BB), 256, G1_SMEM>>>(value_in, nullptr, nullptr,
        mkT(SS, BB*DD, SS, DD, 1, 1, 0,  DD,0,  MH*SS,0,  MH*DD,0,  0,0,  0, O_SC, O_U));

    // K5 (fp32): ao[m][b,h64+j] = sum_k u[b][mh,k]*Wv[m][k,h64+j] + bv
    gemm_nn<<<dim3(1, 1, MM*HH), 256>>>(nullptr, Wv, bv,
        mk(HD, DD, MH*DD, DD, DD, HH, 1,  HH*DD,DD,  DD*DD,HD,  BB*DD,HD,  DD,HD,  O_U, O_AO));

    // K6: x[:, :D] = relu(ao @ Wo + bo)               (single tf32, trans, K=512)
    mma_gemm1<<<dim3(4, 1, MM), 256, G1_SMEM>>>(Wo, nullptr, bo,
        mkT(DD, DD, DD, 2*DD, 1, 1, 2,  DD*DD,0,  BB*DD,0,  BB*2*DD,0,  DD,0,  0, O_AO, O_X));

    xfill_k<<<(MM*BB*DD)/256, 256>>>(prev_state);

    // K7a: h = relu(x @ W1 + b1)                      (single tf32, trans, K=1024)
    mma_gemm1<<<dim3(8, 1, GG*MM), 256, G1_SMEM>>>(W1, nullptr, b1,
        mkT(2*DD, FF, 2*DD, FF, MM, 1, 2,
            MM*2*DD*FF, 2*DD*FF,  0, BB*2*DD,  MM*BB*FF, BB*FF,  MM*FF, FF,  0, O_X, O_H));

    // K7b: hg = relu(x @ Wg1 + bg1)
    mma_gemm1<<<dim3(8, 1, GG*MM), 256, G1_SMEM>>>(Wg1, nullptr, bg1,
        mkT(2*DD, FF, 2*DD, FF, MM, 1, 2,
            MM*2*DD*FF, 2*DD*FF,  0, BB*2*DD,  MM*BB*FF, BB*FF,  MM*FF, FF,  0, O_X, O_HG));

    // K8a: ob = tanh(relu(h @ W2 + b2))               (single tf32, trans, K=1024)
    mma_gemm1<<<dim3(4, 1, GG*MM), 256, G1_SMEM>>>(W2, nullptr, b2,
        mkT(FF, DD, FF, DD, MM, 1, 3,
            MM*FF*DD, FF*DD,  MM*BB*FF, BB*FF,  MM*BB*DD, BB*DD,  MM*DD, DD,  0, O_H, O_OB));

    gate_k<<<GG*MM*BB/8, 256>>>(Wg2, bg2);

    final_k<<<(GG*MM*BB*DD)/256, 256>>>(prev_query, prev_key, prev_value, prev_state,
                                        (float*)d_out);
}

// round 9
// speedup vs baseline: 2.1240x; 1.0632x over previous
#include <cuda_runtime.h>
#include <math.h>
#include <stdint.h>

#define MM 8
#define BB 64
#define SS 128
#define DD 512
#define HH 8
#define FF 1024
#define HD 64
#define MH 64
#define GG 4

#define O_Q   0u
#define O_TQ  262144u
#define O_SC  2359296u
#define O_U   2883584u
#define O_AO  4980736u
#define O_X   5242880u
#define O_H   5767168u
#define O_HG  7864320u
#define O_OB  9961472u
#define O_GT  11010048u
#define SCRATCH_ELEMS 11012096u

__device__ float g_buf[SCRATCH_ELEMS];

// ===================== helpers =====================
__device__ __forceinline__ uint32_t t32(float x) {
    uint32_t r;
    asm("cvt.rna.tf32.f32 %0, %1;" : "=r"(r) : "f"(x));
    return r;
}

__device__ __forceinline__ void mma8(float* c, const uint32_t* a, uint32_t b0, uint32_t b1) {
    asm volatile("mma.sync.aligned.m16n8k8.row.col.f32.tf32.tf32.f32 "
        "{%0,%1,%2,%3}, {%4,%5,%6,%7}, {%8,%9}, {%0,%1,%2,%3};"
        : "+f"(c[0]), "+f"(c[1]), "+f"(c[2]), "+f"(c[3])
        : "r"(a[0]), "r"(a[1]), "r"(a[2]), "r"(a[3]), "r"(b0), "r"(b1));
}

// D[f,b] = sum_k W[f,k]*A[b,k]; C[b*ldc+f]
// trans=1: W gmem [k][f]; trans=0: W gmem [f][k].
// epi: 0 none, 1 +bias, 2 relu+bias, 3 tanh(relu+bias)
// dual mode: if oC2 != ~0u, grid.z is doubled; second half uses Wg2/bias2/oC2.
struct TGP {
    int K, ldW, ldA, ldc, n2, trans, epi, zhalf;
    int sW1, sW2, sA1, sA2, sC1, sC2, sb1, sb2;
    unsigned oW, oA, oC, oC2;
};

// ===================== single-product tf32 GEMM (K-tile 32, double-buffered) ==
#define G1A 4608u                  // 128*36 words per A stage
#define G1B 2304u                  // 64*36 words per B stage
#define G1_SMEM ((G1A + G1B) * 2u * 4u)   // 55296 B

__global__ __launch_bounds__(256) void mma_gemm1(
    const float* __restrict__ Wg, const float* __restrict__ Ag,
    const float* __restrict__ bias,
    const float* __restrict__ Wg2, const float* __restrict__ bias2, TGP p)
{
    extern __shared__ uint32_t sm1[];
    uint32_t* AsB[2] = {sm1, sm1 + G1A};
    uint32_t* BsB[2] = {sm1 + 2u * G1A, sm1 + 2u * G1A + G1B};

    int tid = threadIdx.x, wid = tid >> 5, lane = tid & 31;
    int tg = lane >> 2, tq = lane & 3;

    int z = blockIdx.z;
    const float* Wbase = Wg;
    const float* bbase = bias;
    unsigned oC = p.oC;
    if (p.oC2 != 0xFFFFFFFFu && z >= p.zhalf) {
        z -= p.zhalf;
        Wbase = Wg2;
        bbase = bias2;
        oC = p.oC2;
    }
    int z1 = z / p.n2, z2 = z - z1 * p.n2;
    int f0 = blockIdx.x * 128;

    const float* Wp = (Wbase ? Wbase : g_buf + p.oW) + (size_t)z1 * p.sW1 + (size_t)z2 * p.sW2;
    const float* Ap = (Ag ? Ag : g_buf + p.oA) + (size_t)z1 * p.sA1 + (size_t)z2 * p.sA2;
    float*       Cp = g_buf + oC + (size_t)z1 * p.sC1 + (size_t)z2 * p.sC2;

    int fw = (wid & 3) * 32, bw = (wid >> 2) * 32;
    float acc[2][4][4];
#pragma unroll
    for (int i = 0; i < 2; i++)
#pragma unroll
        for (int j = 0; j < 4; j++)
#pragma unroll
            for (int r = 0; r < 4; r++) acc[i][j][r] = 0.f;

    float4 wv[4], av[2];

    auto LDG = [&](int kk) {
        if (p.trans) {
#pragma unroll
            for (int i = 0; i < 4; i++) {
                int k = (tid >> 5) + 8 * i;
                wv[i] = *(const float4*)&Wp[(size_t)(kk + k) * p.ldW + f0 + 4 * lane];
            }
        } else {
#pragma unroll
            for (int i = 0; i < 4; i++) {
                int idx = tid + 256 * i;
                int f = idx >> 3, kq = (idx & 7) * 4;
                wv[i] = *(const float4*)&Wp[(size_t)(f0 + f) * p.ldW + kk + kq];
            }
        }
#pragma unroll
        for (int i = 0; i < 2; i++) {
            int idx = tid + 256 * i;
            int b = idx >> 3, kq = (idx & 7) * 4;
            av[i] = *(const float4*)&Ap[(size_t)b * p.ldA + kk + kq];
        }
    };

    auto STS = [&](uint32_t* As, uint32_t* Bs) {
        if (p.trans) {
#pragma unroll
            for (int i = 0; i < 4; i++) {
                int k = (tid >> 5) + 8 * i;
                float w4[4] = {wv[i].x, wv[i].y, wv[i].z, wv[i].w};
#pragma unroll
                for (int j = 0; j < 4; j++) {
                    int c = (j + lane) & 3;
                    As[(4 * lane + c) * 36 + k] = t32(w4[c]);
                }
            }
        } else {
#pragma unroll
            for (int i = 0; i < 4; i++) {
                int idx = tid + 256 * i;
                int f = idx >> 3, kq = (idx & 7) * 4;
                As[f * 36 + kq + 0] = t32(wv[i].x);
                As[f * 36 + kq + 1] = t32(wv[i].y);
                As[f * 36 + kq + 2] = t32(wv[i].z);
                As[f * 36 + kq + 3] = t32(wv[i].w);
            }
        }
#pragma unroll
        for (int i = 0; i < 2; i++) {
            int idx = tid + 256 * i;
            int b = idx >> 3, kq = (idx & 7) * 4;
            Bs[b * 36 + kq + 0] = t32(av[i].x);
            Bs[b * 36 + kq + 1] = t32(av[i].y);
            Bs[b * 36 + kq + 2] = t32(av[i].z);
            Bs[b * 36 + kq + 3] = t32(av[i].w);
        }
    };

    auto CMP = [&](const uint32_t* As, const uint32_t* Bs) {
#pragma unroll
        for (int s = 0; s < 4; s++) {
            uint32_t a[2][4], bq[4][2];
#pragma unroll
            for (int i = 0; i < 2; i++) {
                int fb = fw + 16 * i + tg;
                a[i][0] = As[fb * 36 + 8 * s + tq];
                a[i][1] = As[(fb + 8) * 36 + 8 * s + tq];
                a[i][2] = As[fb * 36 + 8 * s + tq + 4];
                a[i][3] = As[(fb + 8) * 36 + 8 * s + tq + 4];
            }
#pragma unroll
            for (int j = 0; j < 4; j++) {
                int nb = bw + 8 * j + tg;
                bq[j][0] = Bs[nb * 36 + 8 * s + tq];
                bq[j][1] = Bs[nb * 36 + 8 * s + tq + 4];
            }
#pragma unroll
            for (int i = 0; i < 2; i++)
#pragma unroll
                for (int j = 0; j < 4; j++)
                    mma8(acc[i][j], a[i], bq[j][0], bq[j][1]);
        }
    };

    int nt = p.K >> 5;
    LDG(0);
    STS(AsB[0], BsB[0]);
    __syncthreads();
    for (int t = 0; t < nt; t++) {
        if (t + 1 < nt) LDG((t + 1) << 5);
        CMP(AsB[t & 1], BsB[t & 1]);
        if (t + 1 < nt) STS(AsB[(t + 1) & 1], BsB[(t + 1) & 1]);
        __syncthreads();
    }

    const float* bp = (p.epi >= 1) ? bbase + (size_t)z1 * p.sb1 + (size_t)z2 * p.sb2 : nullptr;
#pragma unroll
    for (int i = 0; i < 2; i++) {
        int fr = f0 + fw + 16 * i + tg, frh = fr + 8;
        float bv0 = bp ? bp[fr] : 0.f, bv1 = bp ? bp[frh] : 0.f;
#pragma unroll
        for (int j = 0; j < 4; j++) {
            int bc = bw + 8 * j + 2 * tq;
            float v0 = acc[i][j][0] + bv0, v1 = acc[i][j][1] + bv0;
            float v2 = acc[i][j][2] + bv1, v3 = acc[i][j][3] + bv1;
            if (p.epi == 2) {
                v0 = fmaxf(v0, 0.f); v1 = fmaxf(v1, 0.f);
                v2 = fmaxf(v2, 0.f); v3 = fmaxf(v3, 0.f);
            } else if (p.epi == 3) {
                v0 = tanhf(fmaxf(v0, 0.f)); v1 = tanhf(fmaxf(v1, 0.f));
                v2 = tanhf(fmaxf(v2, 0.f)); v3 = tanhf(fmaxf(v3, 0.f));
            }
            Cp[(size_t)bc * p.ldc + fr]        = v0;
            Cp[(size_t)(bc + 1) * p.ldc + fr]  = v1;
            Cp[(size_t)bc * p.ldc + frh]       = v2;
            Cp[(size_t)(bc + 1) * p.ldc + frh] = v3;
        }
    }
}

// ===================== fp32 SGEMM (K5 only) =====================
struct GP {
    int N, K, lda, ldb, ldc, n2, epi;
    int sA1, sA2, sB1, sB2, sC1, sC2, sb1, sb2;
    unsigned oA, oC;
};

__global__ __launch_bounds__(256) void gemm_nn(
    const float* __restrict__ Ain, const float* __restrict__ Bm,
    const float* __restrict__ bias, GP p)
{
    __shared__ float As[16][68];
    __shared__ float Bs[16][132];
    const float* A = Ain ? Ain : g_buf + p.oA;
    float*       C = g_buf + p.oC;
    int z = blockIdx.z, z1 = z / p.n2, z2 = z - z1 * p.n2;
    A  += (size_t)z1 * p.sA1 + (size_t)z2 * p.sA2;
    Bm += (size_t)z1 * p.sB1 + (size_t)z2 * p.sB2;
    C  += (size_t)z1 * p.sC1 + (size_t)z2 * p.sC2;
    int n0 = blockIdx.x * 128, tid = threadIdx.x, tx = tid & 15, ty = tid >> 4;
    float acc[4][8];
#pragma unroll
    for (int i = 0; i < 4; i++)
#pragma unroll
        for (int j = 0; j < 8; j++) acc[i][j] = 0.f;
    int a_row = tid >> 2, a_k4 = (tid & 3) * 4;
    for (int kk = 0; kk < p.K; kk += 16) {
        float4 av = *(const float4*)&A[a_row * (size_t)p.lda + kk + a_k4];
        float4 bv[2];
#pragma unroll
        for (int t = 0; t < 2; t++) {
            int idx = tid + 256 * t, bk = idx >> 5, bn4 = (idx & 31) * 4;
            bv[t] = (n0 + bn4 < p.N) ? *(const float4*)&Bm[(kk + bk) * (size_t)p.ldb + n0 + bn4]
                                     : make_float4(0.f, 0.f, 0.f, 0.f);
        }
        __syncthreads();
        As[a_k4 + 0][a_row] = av.x; As[a_k4 + 1][a_row] = av.y;
        As[a_k4 + 2][a_row] = av.z; As[a_k4 + 3][a_row] = av.w;
#pragma unroll
        for (int t = 0; t < 2; t++) {
            int idx = tid + 256 * t, bk = idx >> 5, bn4 = (idx & 31) * 4;
            *(float4*)&Bs[bk][bn4] = bv[t];
        }
        __syncthreads();
#pragma unroll
        for (int k = 0; k < 16; k++) {
            float4 af = *(const float4*)&As[k][ty << 2];
            float4 b0 = *(const float4*)&Bs[k][tx << 3];
            float4 b1 = *(const float4*)&Bs[k][(tx << 3) + 4];
            float ar[4] = {af.x, af.y, af.z, af.w};
            float br[8] = {b0.x, b0.y, b0.z, b0.w, b1.x, b1.y, b1.z, b1.w};
#pragma unroll
            for (int i = 0; i < 4; i++)
#pragma unroll
                for (int j = 0; j < 8; j++) acc[i][j] += ar[i] * br[j];
        }
    }
    const float* bp = bias ? bias + (size_t)z1 * p.sb1 + (size_t)z2 * p.sb2 : nullptr;
#pragma unroll
    for (int i = 0; i < 4; i++) {
        int r = (ty << 2) + i;
#pragma unroll
        for (int j = 0; j < 8; j++) {
            int c = n0 + (tx << 3) + j;
            if (c < p.N) {
                float v = acc[i][j];
                if (p.epi >= 1) v += bp[c];
                if (p.epi == 2) v = fmaxf(v, 0.f);
                C[r * (size_t)p.ldc + c] = v;
            }
        }
    }
}

// ===================== small kernels =====================
__global__ void softmax_k()
{
    float* sc = g_buf + O_SC;
    int row = blockIdx.x * 8 + (threadIdx.x >> 5), lane = threadIdx.x & 31;
    float4 v = *(float4*)&sc[(size_t)row * SS + lane * 4];
    float mx = fmaxf(fmaxf(v.x, v.y), fmaxf(v.z, v.w));
#pragma unroll
    for (int o = 16; o; o >>= 1) mx = fmaxf(mx, __shfl_xor_sync(0xffffffffu, mx, o));
    float4 e;
    e.x = __expf((v.x - mx) * 0.125f); e.y = __expf((v.y - mx) * 0.125f);
    e.z = __expf((v.z - mx) * 0.125f); e.w = __expf((v.w - mx) * 0.125f);
    float s = e.x + e.y + e.z + e.w;
#pragma unroll
    for (int o = 16; o; o >>= 1) s += __shfl_xor_sync(0xffffffffu, s, o);
    float inv = 1.f / s;
    e.x *= inv; e.y *= inv; e.z *= inv; e.w *= inv;
    *(float4*)&sc[(size_t)row * SS + lane * 4] = e;
}

__global__ void xfill_k(const float* __restrict__ prev_state)
{
    int idx = blockIdx.x * 256 + threadIdx.x;
    if (idx < MM * BB * DD) {
        int mb = idx / DD, j = idx - mb * DD;
        g_buf[O_X + (size_t)mb * (2 * DD) + DD + j] = fmaxf(prev_state[idx], 0.f);
    }
}

__global__ void gate_k(const float* __restrict__ Wg2, const float* __restrict__ bg2)
{
    int row = blockIdx.x * 8 + (threadIdx.x >> 5), lane = threadIdx.x & 31;
    int gm = row / BB;
    const float* hg = g_buf + O_HG + (size_t)row * FF;
    const float* w  = &Wg2[(size_t)gm * FF];
    float s = 0.f;
#pragma unroll
    for (int f = lane * 4; f < FF; f += 128) {
        float4 a = *(const float4*)&hg[f];
        float4 b = *(const float4*)&w[f];
        s += a.x * b.x + a.y * b.y + a.z * b.z + a.w * b.w;
    }
#pragma unroll
    for (int o = 16; o; o >>= 1) s += __shfl_xor_sync(0xffffffffu, s, o);
    if (lane == 0)
        g_buf[O_GT + row] = 1.f / (1.f + __expf(-(s + bg2[gm])));
}

__global__ void final_k(const float* __restrict__ pq, const float* __restrict__ pk,
                        const float* __restrict__ pv, const float* __restrict__ ps,
                        float* __restrict__ out)
{
    int idx = blockIdx.x * 256 + threadIdx.x;
    int o = idx / (MM * BB * DD);
    int rem = idx - o * (MM * BB * DD);
    int mb = rem / DD;
    int g = (o == 0) ? 3 : (o - 1);
    const float* prev = (o == 0) ? ps : (o == 1) ? pq : (o == 2) ? pk : pv;
    float gt = g_buf[O_GT + g * MM * BB + mb];
    float ov = g_buf[O_OB + (size_t)g * MM * BB * DD + rem];
    out[idx] = gt * ov + (1.f - gt) * prev[rem];
}

// ===================== launch =====================
static TGP mkT(int K, int ldW, int ldA, int ldc, int n2, int trans, int epi,
               int sW1, int sW2, int sA1, int sA2, int sC1, int sC2, int sb1, int sb2,
               unsigned oW, unsigned oA, unsigned oC,
               unsigned oC2 = 0xFFFFFFFFu, int zhalf = 0)
{
    TGP p; p.K = K; p.ldW = ldW; p.ldA = ldA; p.ldc = ldc; p.n2 = n2; p.trans = trans; p.epi = epi;
    p.zhalf = zhalf;
    p.sW1 = sW1; p.sW2 = sW2; p.sA1 = sA1; p.sA2 = sA2; p.sC1 = sC1; p.sC2 = sC2;
    p.sb1 = sb1; p.sb2 = sb2; p.oW = oW; p.oA = oA; p.oC = oC; p.oC2 = oC2;
    return p;
}
static GP mk(int N, int K, int lda, int ldb, int ldc, int n2, int epi,
             int sA1, int sA2, int sB1, int sB2, int sC1, int sC2, int sb1, int sb2,
             unsigned oA, unsigned oC)
{
    GP p; p.N = N; p.K = K; p.lda = lda; p.ldb = ldb; p.ldc = ldc; p.n2 = n2; p.epi = epi;
    p.sA1 = sA1; p.sA2 = sA2; p.sB1 = sB1; p.sB2 = sB2; p.sC1 = sC1; p.sC2 = sC2;
    p.sb1 = sb1; p.sb2 = sb2; p.oA = oA; p.oC = oC;
    return p;
}

extern "C" void kernel_launch(void* const* d_in, const int* in_sizes, int n_in,
                              void* d_out, int out_size)
{
    const float* prev_state = (const float*)d_in[0];
    const float* prev_query = (const float*)d_in[1];
    const float* prev_key   = (const float*)d_in[2];
    const float* prev_value = (const float*)d_in[3];
    const float* key_in     = (const float*)d_in[4];
    const float* value_in   = (const float*)d_in[5];
    const float* Wq  = (const float*)d_in[6];
    const float* bq  = (const float*)d_in[7];
    const float* Wk  = (const float*)d_in[8];
    // bk (d_in[9]) dead: constant over s -> softmax-invariant
    const float* Wv  = (const float*)d_in[10];
    const float* bv  = (const float*)d_in[11];
    const float* Wo  = (const float*)d_in[12];
    const float* bo  = (const float*)d_in[13];
    const float* W1  = (const float*)d_in[14];
    const float* b1  = (const float*)d_in[15];
    const float* W2  = (const float*)d_in[16];
    const float* b2  = (const float*)d_in[17];
    const float* Wg1 = (const float*)d_in[18];
    const float* bg1 = (const float*)d_in[19];
    const float* Wg2 = (const float*)d_in[20];
    const float* bg2 = (const float*)d_in[21];

    cudaFuncSetAttribute(mma_gemm1, cudaFuncAttributeMaxDynamicSharedMemorySize, G1_SMEM);

    // xfill first (independent of attention chain)
    xfill_k<<<(MM*BB*DD)/256, 256>>>(prev_state);

    // K1: q[m][b,f] = prev_query[m] @ Wq[m] + bq     (trans, K=512)
    mma_gemm1<<<dim3(4, 1, MM), 256, G1_SMEM>>>(Wq, prev_query, bq, nullptr, nullptr,
        mkT(DD, DD, DD, DD, 1, 1, 1,  DD*DD,0,  BB*DD,0,  BB*DD,0,  DD,0,  0,0, O_Q));

    // K2: tq[b][mh][kin] = sum_j q[m][b,h64+j]*Wk[m][kin][h64+j]  (no-trans, K=64)
    mma_gemm1<<<dim3(4, 1, MM*HH), 256, G1_SMEM>>>(Wk, nullptr, nullptr, nullptr, nullptr,
        mkT(HD, DD, DD, MH*DD, HH, 0, 0,  DD*DD,HD,  BB*DD,HD,  HH*DD,DD,  0,0,  0, O_Q, O_TQ));

    // K3: sc[b][mh][s] = key_in[s,b,:] . tq[b][mh,:]  (no-trans, K=512, f=s)
    mma_gemm1<<<dim3(1, 1, BB), 256, G1_SMEM>>>(key_in, nullptr, nullptr, nullptr, nullptr,
        mkT(DD, BB*DD, DD, SS, 1, 0, 0,  DD,0,  MH*DD,0,  MH*SS,0,  0,0,  0, O_TQ, O_SC));

    softmax_k<<<BB*MH/8, 256>>>();

    // K4: u[b][mh][k] = sum_s w[b][mh,s]*value_in[s,b,k]  (trans, K=128)
    mma_gemm1<<<dim3(4, 1, BB), 256, G1_SMEM>>>(value_in, nullptr, nullptr, nullptr, nullptr,
        mkT(SS, BB*DD, SS, DD, 1, 1, 0,  DD,0,  MH*SS,0,  MH*DD,0,  0,0,  0, O_SC, O_U));

    // K5 (fp32): ao[m][b,h64+j] = sum_k u[b][mh,k]*Wv[m][k,h64+j] + bv
    gemm_nn<<<dim3(1, 1, MM*HH), 256>>>(nullptr, Wv, bv,
        mk(HD, DD, MH*DD, DD, DD, HH, 1,  HH*DD,DD,  DD*DD,HD,  BB*DD,HD,  DD,HD,  O_U, O_AO));

    // K6: x[:, :D] = relu(ao @ Wo + bo)               (trans, K=512)
    mma_gemm1<<<dim3(4, 1, MM), 256, G1_SMEM>>>(Wo, nullptr, bo, nullptr, nullptr,
        mkT(DD, DD, DD, 2*DD, 1, 1, 2,  DD*DD,0,  BB*DD,0,  BB*2*DD,0,  DD,0,  0, O_AO, O_X));

    // K7 merged: h = relu(x@W1+b1), hg = relu(x@Wg1+bg1)  (trans, K=1024, dual z)
    mma_gemm1<<<dim3(8, 1, 2*GG*MM), 256, G1_SMEM>>>(W1, nullptr, b1, Wg1, bg1,
        mkT(2*DD, FF, 2*DD, FF, MM, 1, 2,
            MM*2*DD*FF, 2*DD*FF,  0, BB*2*DD,  MM*BB*FF, BB*FF,  MM*FF, FF,
            0, O_X, O_H, O_HG, GG*MM));

    // K8a: ob = tanh(relu(h @ W2 + b2))               (trans, K=1024)
    mma_gemm1<<<dim3(4, 1, GG*MM), 256, G1_SMEM>>>(W2, nullptr, b2, nullptr, nullptr,
        mkT(FF, DD, FF, DD, MM, 1, 3,
            MM*FF*DD, FF*DD,  MM*BB*FF, BB*FF,  MM*BB*DD, BB*DD,  MM*DD, DD,  0, O_H, O_OB));

    gate_k<<<GG*MM*BB/8, 256>>>(Wg2, bg2);

    final_k<<<(GG*MM*BB*DD)/256, 256>>>(prev_query, prev_key, prev_value, prev_state,
                                        (float*)d_out);
}